// round 6
// baseline (speedup 1.0000x reference)
#include <cuda_runtime.h>
#include <cstdint>
#include <cmath>

#define B_  256
#define T_  128
#define D_  256
#define H1  512
#define G1  (4*H1)
#define H2  1024
#define G2  (4*H2)

__device__ float g_igf [(size_t)T_*B_*G1];
__device__ float g_igb [(size_t)T_*B_*G1];
__device__ float g_igs [(size_t)T_*B_*G2];
__device__ float g_comb[(size_t)T_*B_*(2*H1)];
__device__ float g_zero[B_*H2];
__device__ float g_h2a [B_*H2];
__device__ float g_h2b [B_*H2];
__device__ unsigned g_bars[2];

__device__ __forceinline__ float cvt_tf32(float x) {
    uint32_t u; asm("cvt.rna.tf32.f32 %0, %1;" : "=r"(u) : "f"(x));
    return __uint_as_float(u);
}
__device__ __forceinline__ void mma_tf32(float& d0, float& d1, float& d2, float& d3,
                                         uint32_t a0, uint32_t a1, uint32_t a2, uint32_t a3,
                                         uint32_t b0, uint32_t b1) {
    asm volatile("mma.sync.aligned.m16n8k8.row.col.f32.tf32.tf32.f32 "
        "{%0,%1,%2,%3}, {%4,%5,%6,%7}, {%8,%9}, {%0,%1,%2,%3};\n"
        : "+f"(d0), "+f"(d1), "+f"(d2), "+f"(d3)
        : "r"(a0), "r"(a1), "r"(a2), "r"(a3), "r"(b0), "r"(b1));
}
__device__ __forceinline__ float sigm_(float x) { return 1.0f / (1.0f + expf(-x)); }

// ---------------------------------------------------------------------------
// GEMM: out[orow(m)][n] = sum_k A[m][k]*W[n][k].
// BM=128, BN=128, BK=16, 256 thr, warps 2x4, warp tile 64x32.
// remap: 0 identity; 1 fwd time-major; 2 reversed time-major.
// ---------------------------------------------------------------------------
__global__ void __launch_bounds__(256, 2) gemm_tf32_nt(
    const float* __restrict__ A, const float* __restrict__ W,
    float* __restrict__ out, int M, int N, int K, int remap)
{
    constexpr int BK = 16;
    __shared__ float As[128][BK + 1];
    __shared__ float Bs[128][BK + 1];
    const int tid = threadIdx.x, lane = tid & 31, warp = tid >> 5;
    const int gid = lane >> 2, tig = lane & 3;
    const int wm = warp >> 2, wn = warp & 3;          // 2 x 4
    const int bm0 = blockIdx.y * 128, bn0 = blockIdx.x * 128;

    float acc[4][4][4];
#pragma unroll
    for (int a = 0; a < 4; a++)
#pragma unroll
        for (int b = 0; b < 4; b++)
#pragma unroll
            for (int c = 0; c < 4; c++) acc[a][b][c] = 0.f;

    const int kIters = K / BK;
    float4 pa[2], pb[2];
#pragma unroll
    for (int j = 0; j < 2; j++) { int i = tid + j*256, r = i>>2, c = i&3;
        pa[j] = *(const float4*)(A + (size_t)(bm0+r)*K + c*4);
        pb[j] = *(const float4*)(W + (size_t)(bn0+r)*K + c*4); }

    for (int kt = 0; kt < kIters; kt++) {
#pragma unroll
        for (int j = 0; j < 2; j++) { int i = tid + j*256, r = i>>2, c = i&3;
            As[r][c*4+0]=cvt_tf32(pa[j].x); As[r][c*4+1]=cvt_tf32(pa[j].y);
            As[r][c*4+2]=cvt_tf32(pa[j].z); As[r][c*4+3]=cvt_tf32(pa[j].w);
            Bs[r][c*4+0]=cvt_tf32(pb[j].x); Bs[r][c*4+1]=cvt_tf32(pb[j].y);
            Bs[r][c*4+2]=cvt_tf32(pb[j].z); Bs[r][c*4+3]=cvt_tf32(pb[j].w); }
        __syncthreads();
        if (kt + 1 < kIters) {
            int k0 = (kt+1)*BK;
#pragma unroll
            for (int j = 0; j < 2; j++) { int i = tid + j*256, r = i>>2, c = i&3;
                pa[j] = *(const float4*)(A + (size_t)(bm0+r)*K + k0 + c*4);
                pb[j] = *(const float4*)(W + (size_t)(bn0+r)*K + k0 + c*4); }
        }
#pragma unroll
        for (int kc = 0; kc < 2; kc++) {
            uint32_t af[4][4];
#pragma unroll
            for (int mt = 0; mt < 4; mt++) {
                int r = wm*64 + mt*16;
                af[mt][0] = __float_as_uint(As[r+gid  ][kc*8+tig  ]);
                af[mt][1] = __float_as_uint(As[r+gid+8][kc*8+tig  ]);
                af[mt][2] = __float_as_uint(As[r+gid  ][kc*8+tig+4]);
                af[mt][3] = __float_as_uint(As[r+gid+8][kc*8+tig+4]);
            }
#pragma unroll
            for (int nt = 0; nt < 4; nt++) {
                int cc = wn*32 + nt*8;
                uint32_t b0 = __float_as_uint(Bs[cc+gid][kc*8+tig  ]);
                uint32_t b1 = __float_as_uint(Bs[cc+gid][kc*8+tig+4]);
#pragma unroll
                for (int mt = 0; mt < 4; mt++)
                    mma_tf32(acc[mt][nt][0],acc[mt][nt][1],acc[mt][nt][2],acc[mt][nt][3],
                             af[mt][0],af[mt][1],af[mt][2],af[mt][3], b0, b1);
            }
        }
        __syncthreads();
    }
#pragma unroll
    for (int mt = 0; mt < 4; mt++)
#pragma unroll
        for (int half = 0; half < 2; half++) {
            int m = bm0 + wm*64 + mt*16 + gid + half*8;
            int orow;
            if (remap == 0) orow = m;
            else { int t = m % T_, b = m / T_;
                   orow = ((remap == 1) ? t : (T_-1-t)) * B_ + b; }
            float* op = out + (size_t)orow*N + bn0 + wn*32 + 2*tig;
#pragma unroll
            for (int nt = 0; nt < 4; nt++) {
                op[nt*8+0] = acc[mt][nt][half*2+0];
                op[nt*8+1] = acc[mt][nt][half*2+1];
            }
        }
}

// ---------------------------------------------------------------------------
// Persistent LSTM scan. One launch for all T steps; software grid barrier.
// grid = NDIR * (B/64) * (HD/32) = 128 blocks (<=148 SMs, all co-resident).
// block = 512 threads = 16 warps; warp = (mtile = warp>>2, gate = warp&3).
// c-state lives in registers. MODE 0: h history in hist (stride 2*HD, diroff
// HD per direction). MODE 1: ping-pong h2a/h2b.
// ---------------------------------------------------------------------------
template <int HD, int NDIR, int MODE>
__global__ void __launch_bounds__(512, 1) lstm_scan(
    const float* __restrict__ Whh_f, const float* __restrict__ Whh_b,
    const float* __restrict__ bias_f, const float* __restrict__ bias_b,
    const float* __restrict__ igf, const float* __restrict__ igb,
    const float* __restrict__ h0,
    float* __restrict__ hist, float* __restrict__ h2a, float* __restrict__ h2b,
    unsigned* __restrict__ bar)
{
    __shared__ float As[64][33];
    __shared__ float Bs[128][33];
    __shared__ float gsh[64][129];
    __shared__ float bsh[128];

    const int tid = threadIdx.x, lane = tid & 31, warp = tid >> 5;
    const int gid = lane >> 2, tig = lane & 3;
    const int g = warp & 3, mt = warp >> 2;

    const int tilesJ = HD / 32, tilesB = B_ / 64;
    const int dir = blockIdx.x / (tilesB * tilesJ);
    const int rem = blockIdx.x % (tilesB * tilesJ);
    const int m0  = (rem / tilesJ) * 64;
    const int j0  = (rem % tilesJ) * 32;

    const float* Whh  = dir ? Whh_b  : Whh_f;
    const float* bias = dir ? bias_b : bias_f;
    const float* ig   = dir ? igb    : igf;

    const int hstride = (MODE == 0) ? 2*HD : HD;
    const int hdiroff = (MODE == 0) ? dir*HD : 0;

    if (tid < 128) bsh[tid] = bias[(tid>>5)*HD + j0 + (tid&31)];
    __syncthreads();

    float c_reg[4] = {0.f, 0.f, 0.f, 0.f};
    const int kIters = HD / 32;
    const unsigned nblk = gridDim.x;

    for (int t = 0; t < T_; t++) {
        const float* hp;
        float* hn;
        if (MODE == 0) {
            hp = (t == 0) ? h0 : hist + (size_t)(t-1)*B_*(2*HD);
            hn = hist + (size_t)t*B_*(2*HD);
        } else {
            hp = (t == 0) ? h0 : ((t & 1) ? h2a : h2b);
            hn = (t & 1) ? h2b : h2a;
        }

        float acc[4][4];
#pragma unroll
        for (int a = 0; a < 4; a++)
#pragma unroll
            for (int b = 0; b < 4; b++) acc[a][b] = 0.f;

        float4 pa, pb[2];
        {   // prefetch k-tile 0 (h via L2-only loads: L1 is stale across blocks)
            int r = tid >> 3, c = tid & 7;
            pa = __ldcg((const float4*)(hp + (size_t)(m0+r)*hstride + hdiroff + c*4));
#pragma unroll
            for (int j = 0; j < 2; j++) {
                int i = tid + j*512, n = i>>3, cc = i&7;
                int grow = (n>>5)*HD + j0 + (n&31);
                pb[j] = *(const float4*)(Whh + (size_t)grow*HD + cc*4);
            }
        }

        for (int kt = 0; kt < kIters; kt++) {
            {
                int r = tid >> 3, c = tid & 7;
                As[r][c*4+0]=cvt_tf32(pa.x); As[r][c*4+1]=cvt_tf32(pa.y);
                As[r][c*4+2]=cvt_tf32(pa.z); As[r][c*4+3]=cvt_tf32(pa.w);
#pragma unroll
                for (int j = 0; j < 2; j++) {
                    int i = tid + j*512, n = i>>3, cc = i&7;
                    Bs[n][cc*4+0]=cvt_tf32(pb[j].x); Bs[n][cc*4+1]=cvt_tf32(pb[j].y);
                    Bs[n][cc*4+2]=cvt_tf32(pb[j].z); Bs[n][cc*4+3]=cvt_tf32(pb[j].w);
                }
            }
            __syncthreads();
            if (kt + 1 < kIters) {
                int k0 = (kt+1)*32;
                int r = tid >> 3, c = tid & 7;
                pa = __ldcg((const float4*)(hp + (size_t)(m0+r)*hstride + hdiroff + k0 + c*4));
#pragma unroll
                for (int j = 0; j < 2; j++) {
                    int i = tid + j*512, n = i>>3, cc = i&7;
                    int grow = (n>>5)*HD + j0 + (n&31);
                    pb[j] = *(const float4*)(Whh + (size_t)grow*HD + k0 + cc*4);
                }
            }
#pragma unroll
            for (int kc = 0; kc < 4; kc++) {
                uint32_t a0 = __float_as_uint(As[mt*16+gid  ][kc*8+tig  ]);
                uint32_t a1 = __float_as_uint(As[mt*16+gid+8][kc*8+tig  ]);
                uint32_t a2 = __float_as_uint(As[mt*16+gid  ][kc*8+tig+4]);
                uint32_t a3 = __float_as_uint(As[mt*16+gid+8][kc*8+tig+4]);
#pragma unroll
                for (int nt = 0; nt < 4; nt++) {
                    int br = g*32 + nt*8 + gid;
                    uint32_t b0 = __float_as_uint(Bs[br][kc*8+tig  ]);
                    uint32_t b1 = __float_as_uint(Bs[br][kc*8+tig+4]);
                    mma_tf32(acc[nt][0],acc[nt][1],acc[nt][2],acc[nt][3],
                             a0,a1,a2,a3,b0,b1);
                }
            }
            __syncthreads();
        }

#pragma unroll
        for (int nt = 0; nt < 4; nt++) {
            int col = g*32 + nt*8 + 2*tig;
            gsh[mt*16+gid  ][col  ] = acc[nt][0];
            gsh[mt*16+gid  ][col+1] = acc[nt][1];
            gsh[mt*16+gid+8][col  ] = acc[nt][2];
            gsh[mt*16+gid+8][col+1] = acc[nt][3];
        }
        __syncthreads();

#pragma unroll
        for (int s = 0; s < 4; s++) {
            int i = tid + s*512;
            int row = i >> 5, jj = i & 31;
            int b = m0 + row, j = j0 + jj;
            size_t igbase = ((size_t)t*B_ + b) * (size_t)(4*HD);
            float gi = gsh[row][      jj] + ig[igbase + 0*HD + j] + bsh[      jj];
            float gf = gsh[row][ 32 + jj] + ig[igbase + 1*HD + j] + bsh[ 32 + jj];
            float gg = gsh[row][ 64 + jj] + ig[igbase + 2*HD + j] + bsh[ 64 + jj];
            float go = gsh[row][ 96 + jj] + ig[igbase + 3*HD + j] + bsh[ 96 + jj];
            float cn = sigm_(gf)*c_reg[s] + sigm_(gi)*tanhf(gg);
            c_reg[s] = cn;
            hn[(size_t)b*hstride + hdiroff + j] = sigm_(go)*tanhf(cn);
        }

        // grid barrier: make h visible, arrive, spin, acquire
        __threadfence();
        __syncthreads();
        if (tid == 0) {
            atomicAdd(bar, 1u);
            unsigned target = nblk * (unsigned)(t + 1);
            while (*(volatile unsigned*)bar < target) __nanosleep(64);
            __threadfence();
        }
        __syncthreads();
    }
}

__global__ void classifier_kernel(const float* __restrict__ h, const float* __restrict__ Wl,
                                  const float* __restrict__ bl, float* __restrict__ out)
{
    int wid = (blockIdx.x * blockDim.x + threadIdx.x) >> 5;
    int lane = threadIdx.x & 31;
    if (wid >= B_) return;
    const float* hb = h + (size_t)wid * H2;
    float s0 = 0.f, s1 = 0.f;
    for (int j = lane*4; j < H2; j += 128) {
        float4 hv = *(const float4*)(hb + j);
        float4 w0 = *(const float4*)(Wl + j);
        float4 w1 = *(const float4*)(Wl + H2 + j);
        s0 += hv.x*w0.x + hv.y*w0.y + hv.z*w0.z + hv.w*w0.w;
        s1 += hv.x*w1.x + hv.y*w1.y + hv.z*w1.z + hv.w*w1.w;
    }
#pragma unroll
    for (int o = 16; o > 0; o >>= 1) {
        s0 += __shfl_down_sync(0xFFFFFFFFu, s0, o);
        s1 += __shfl_down_sync(0xFFFFFFFFu, s1, o);
    }
    if (lane == 0) {
        out[wid*2+0] = sigm_(s0 + bl[0]);
        out[wid*2+1] = sigm_(s1 + bl[1]);
    }
}

extern "C" void kernel_launch(void* const* d_in, const int* in_sizes, int n_in,
                              void* d_out, int out_size)
{
    (void)in_sizes; (void)n_in; (void)out_size;
    const float* x     = (const float*)d_in[0];
    const float* Wf_ih = (const float*)d_in[1];
    const float* Wf_hh = (const float*)d_in[2];
    const float* bf    = (const float*)d_in[3];
    const float* Wb_ih = (const float*)d_in[4];
    const float* Wb_hh = (const float*)d_in[5];
    const float* bb    = (const float*)d_in[6];
    const float* Ws_ih = (const float*)d_in[7];
    const float* Ws_hh = (const float*)d_in[8];
    const float* bs    = (const float*)d_in[9];
    const float* Wl    = (const float*)d_in[10];
    const float* bl    = (const float*)d_in[11];
    float* out = (float*)d_out;

    float *p_igf,*p_igb,*p_igs,*p_comb,*p_zero,*p_h2a,*p_h2b;
    unsigned* p_bars;
    cudaGetSymbolAddress((void**)&p_igf,  g_igf);
    cudaGetSymbolAddress((void**)&p_igb,  g_igb);
    cudaGetSymbolAddress((void**)&p_igs,  g_igs);
    cudaGetSymbolAddress((void**)&p_comb, g_comb);
    cudaGetSymbolAddress((void**)&p_zero, g_zero);
    cudaGetSymbolAddress((void**)&p_h2a,  g_h2a);
    cudaGetSymbolAddress((void**)&p_h2b,  g_h2b);
    cudaGetSymbolAddress((void**)&p_bars, g_bars);

    cudaMemsetAsync(p_zero, 0, (size_t)B_*H2*sizeof(float));
    cudaMemsetAsync(p_bars, 0, 2*sizeof(unsigned));

    // Input projections (time-independent), rows remapped to time-major.
    gemm_tf32_nt<<<dim3(G1/128, (B_*T_)/128), 256>>>(x, Wf_ih, p_igf, B_*T_, G1, D_, 1);
    gemm_tf32_nt<<<dim3(G1/128, (B_*T_)/128), 256>>>(x, Wb_ih, p_igb, B_*T_, G1, D_, 2);

    // BiLSTM layer 1: persistent, both directions, h written into comb.
    lstm_scan<H1, 2, 0><<<128, 512>>>(Wf_hh, Wb_hh, bf, bb, p_igf, p_igb,
                                      p_zero, p_comb, nullptr, nullptr, p_bars + 0);

    // Input projection for LSTM2.
    gemm_tf32_nt<<<dim3(G2/128, (B_*T_)/128), 256>>>(p_comb, Ws_ih, p_igs, B_*T_, G2, 2*H1, 0);

    // LSTM layer 2: persistent, ping-pong h buffers. Final h ends in h2b (T-1 odd).
    lstm_scan<H2, 1, 1><<<128, 512>>>(Ws_hh, Ws_hh, bs, bs, p_igs, p_igs,
                                      p_zero, nullptr, p_h2a, p_h2b, p_bars + 1);

    classifier_kernel<<<32, 256>>>(p_h2b, Wl, bl, out);
}

// round 8
// speedup vs baseline: 1.1893x; 1.1893x over previous
#include <cuda_runtime.h>
#include <cstdint>
#include <cmath>

#define B_  256
#define T_  128
#define D_  256
#define H1  512
#define G1  (4*H1)
#define H2  1024
#define G2  (4*H2)

__device__ float g_igf [(size_t)T_*B_*G1];
__device__ float g_igb [(size_t)T_*B_*G1];
__device__ float g_igs [(size_t)T_*B_*G2];
__device__ float g_comb[(size_t)T_*B_*(2*H1)];
__device__ float g_zero[B_*H2];
__device__ float g_h2a [B_*H2];
__device__ float g_h2b [B_*H2];
__device__ unsigned g_bars[2];

__device__ __forceinline__ float cvt_tf32(float x) {
    uint32_t u; asm("cvt.rna.tf32.f32 %0, %1;" : "=r"(u) : "f"(x));
    return __uint_as_float(u);
}
__device__ __forceinline__ void mma_tf32(float& d0, float& d1, float& d2, float& d3,
                                         uint32_t a0, uint32_t a1, uint32_t a2, uint32_t a3,
                                         uint32_t b0, uint32_t b1) {
    asm volatile("mma.sync.aligned.m16n8k8.row.col.f32.tf32.tf32.f32 "
        "{%0,%1,%2,%3}, {%4,%5,%6,%7}, {%8,%9}, {%0,%1,%2,%3};\n"
        : "+f"(d0), "+f"(d1), "+f"(d2), "+f"(d3)
        : "r"(a0), "r"(a1), "r"(a2), "r"(a3), "r"(b0), "r"(b1));
}
__device__ __forceinline__ float sigm_(float x) { return 1.0f / (1.0f + expf(-x)); }

// ---------------------------------------------------------------------------
// GEMM (unchanged from R6): out[orow(m)][n] = sum_k A[m][k]*W[n][k].
// BM=128, BN=128, BK=16, 256 thr, warps 2x4, warp tile 64x32.
// ---------------------------------------------------------------------------
__global__ void __launch_bounds__(256, 2) gemm_tf32_nt(
    const float* __restrict__ A, const float* __restrict__ W,
    float* __restrict__ out, int M, int N, int K, int remap)
{
    constexpr int BK = 16;
    __shared__ float As[128][BK + 1];
    __shared__ float Bs[128][BK + 1];
    const int tid = threadIdx.x, lane = tid & 31, warp = tid >> 5;
    const int gid = lane >> 2, tig = lane & 3;
    const int wm = warp >> 2, wn = warp & 3;
    const int bm0 = blockIdx.y * 128, bn0 = blockIdx.x * 128;

    float acc[4][4][4];
#pragma unroll
    for (int a = 0; a < 4; a++)
#pragma unroll
        for (int b = 0; b < 4; b++)
#pragma unroll
            for (int c = 0; c < 4; c++) acc[a][b][c] = 0.f;

    const int kIters = K / BK;
    float4 pa[2], pb[2];
#pragma unroll
    for (int j = 0; j < 2; j++) { int i = tid + j*256, r = i>>2, c = i&3;
        pa[j] = *(const float4*)(A + (size_t)(bm0+r)*K + c*4);
        pb[j] = *(const float4*)(W + (size_t)(bn0+r)*K + c*4); }

    for (int kt = 0; kt < kIters; kt++) {
#pragma unroll
        for (int j = 0; j < 2; j++) { int i = tid + j*256, r = i>>2, c = i&3;
            As[r][c*4+0]=cvt_tf32(pa[j].x); As[r][c*4+1]=cvt_tf32(pa[j].y);
            As[r][c*4+2]=cvt_tf32(pa[j].z); As[r][c*4+3]=cvt_tf32(pa[j].w);
            Bs[r][c*4+0]=cvt_tf32(pb[j].x); Bs[r][c*4+1]=cvt_tf32(pb[j].y);
            Bs[r][c*4+2]=cvt_tf32(pb[j].z); Bs[r][c*4+3]=cvt_tf32(pb[j].w); }
        __syncthreads();
        if (kt + 1 < kIters) {
            int k0 = (kt+1)*BK;
#pragma unroll
            for (int j = 0; j < 2; j++) { int i = tid + j*256, r = i>>2, c = i&3;
                pa[j] = *(const float4*)(A + (size_t)(bm0+r)*K + k0 + c*4);
                pb[j] = *(const float4*)(W + (size_t)(bn0+r)*K + k0 + c*4); }
        }
#pragma unroll
        for (int kc = 0; kc < 2; kc++) {
            uint32_t af[4][4];
#pragma unroll
            for (int mt = 0; mt < 4; mt++) {
                int r = wm*64 + mt*16;
                af[mt][0] = __float_as_uint(As[r+gid  ][kc*8+tig  ]);
                af[mt][1] = __float_as_uint(As[r+gid+8][kc*8+tig  ]);
                af[mt][2] = __float_as_uint(As[r+gid  ][kc*8+tig+4]);
                af[mt][3] = __float_as_uint(As[r+gid+8][kc*8+tig+4]);
            }
#pragma unroll
            for (int nt = 0; nt < 4; nt++) {
                int cc = wn*32 + nt*8;
                uint32_t b0 = __float_as_uint(Bs[cc+gid][kc*8+tig  ]);
                uint32_t b1 = __float_as_uint(Bs[cc+gid][kc*8+tig+4]);
#pragma unroll
                for (int mt = 0; mt < 4; mt++)
                    mma_tf32(acc[mt][nt][0],acc[mt][nt][1],acc[mt][nt][2],acc[mt][nt][3],
                             af[mt][0],af[mt][1],af[mt][2],af[mt][3], b0, b1);
            }
        }
        __syncthreads();
    }
#pragma unroll
    for (int mt = 0; mt < 4; mt++)
#pragma unroll
        for (int half = 0; half < 2; half++) {
            int m = bm0 + wm*64 + mt*16 + gid + half*8;
            int orow;
            if (remap == 0) orow = m;
            else { int t = m % T_, b = m / T_;
                   orow = ((remap == 1) ? t : (T_-1-t)) * B_ + b; }
            float* op = out + (size_t)orow*N + bn0 + wn*32 + 2*tig;
#pragma unroll
            for (int nt = 0; nt < 4; nt++) {
                op[nt*8+0] = acc[mt][nt][half*2+0];
                op[nt*8+1] = acc[mt][nt][half*2+1];
            }
        }
}

// ---------------------------------------------------------------------------
// Persistent LSTM scan, R7 tiling: grid = 64 blocks, block = 512 thr (16 warps).
// Block tile: 128 batch x 32 j x 4 gates. Warp (mq = warp>>2, g = warp&3)
// owns a 32x32 warp tile (2 m16 tiles x 4 n8 tiles of its gate's columns).
// c-state in registers; gate exchange via gsh in two 64-row chunks.
// ---------------------------------------------------------------------------
template <int HD, int NDIR, int MODE>
__global__ void __launch_bounds__(512, 1) lstm_scan(
    const float* __restrict__ Whh_f, const float* __restrict__ Whh_b,
    const float* __restrict__ bias_f, const float* __restrict__ bias_b,
    const float* __restrict__ igf, const float* __restrict__ igb,
    const float* __restrict__ h0,
    float* __restrict__ hist, float* __restrict__ h2a, float* __restrict__ h2b,
    unsigned* __restrict__ bar)
{
    __shared__ float As[128][33];
    __shared__ float Bs[128][33];
    __shared__ float gsh[64][129];
    __shared__ float bsh[128];

    const int tid = threadIdx.x, lane = tid & 31, warp = tid >> 5;
    const int gid = lane >> 2, tig = lane & 3;
    const int g = warp & 3, mq = warp >> 2;      // gate, m-quarter

    const int tilesJ = HD / 32, tilesB = B_ / 128;   // tilesB = 2
    const int dir = blockIdx.x / (tilesB * tilesJ);
    const int rem = blockIdx.x % (tilesB * tilesJ);
    const int m0  = (rem / tilesJ) * 128;
    const int j0  = (rem % tilesJ) * 32;

    const float* Whh  = dir ? Whh_b  : Whh_f;
    const float* bias = dir ? bias_b : bias_f;
    const float* ig   = dir ? igb    : igf;

    const int hstride = (MODE == 0) ? 2*HD : HD;
    const int hdiroff = (MODE == 0) ? dir*HD : 0;

    if (tid < 128) bsh[tid] = bias[(tid>>5)*HD + j0 + (tid&31)];
    __syncthreads();

    float c_reg[2][4] = {{0.f,0.f,0.f,0.f},{0.f,0.f,0.f,0.f}};
    const int kIters = HD / 32;
    const unsigned nblk = gridDim.x;

    for (int t = 0; t < T_; t++) {
        const float* hp;
        float* hn;
        if (MODE == 0) {
            hp = (t == 0) ? h0 : hist + (size_t)(t-1)*B_*(2*HD);
            hn = hist + (size_t)t*B_*(2*HD);
        } else {
            hp = (t == 0) ? h0 : ((t & 1) ? h2a : h2b);
            hn = (t & 1) ? h2b : h2a;
        }

        float acc[2][4][4];
#pragma unroll
        for (int a = 0; a < 2; a++)
#pragma unroll
            for (int b = 0; b < 4; b++)
#pragma unroll
                for (int c = 0; c < 4; c++) acc[a][b][c] = 0.f;

        float4 pa[2], pb[2];
#pragma unroll
        for (int j = 0; j < 2; j++) {
            int i = tid + j*512, r = i>>3, c = i&7;
            pa[j] = __ldcg((const float4*)(hp + (size_t)(m0+r)*hstride + hdiroff + c*4));
            int n = r; int grow = (n>>5)*HD + j0 + (n&31);
            pb[j] = *(const float4*)(Whh + (size_t)grow*HD + c*4);
        }

        for (int kt = 0; kt < kIters; kt++) {
#pragma unroll
            for (int j = 0; j < 2; j++) {
                int i = tid + j*512, r = i>>3, c = i&7;
                As[r][c*4+0]=cvt_tf32(pa[j].x); As[r][c*4+1]=cvt_tf32(pa[j].y);
                As[r][c*4+2]=cvt_tf32(pa[j].z); As[r][c*4+3]=cvt_tf32(pa[j].w);
                Bs[r][c*4+0]=cvt_tf32(pb[j].x); Bs[r][c*4+1]=cvt_tf32(pb[j].y);
                Bs[r][c*4+2]=cvt_tf32(pb[j].z); Bs[r][c*4+3]=cvt_tf32(pb[j].w);
            }
            __syncthreads();
            if (kt + 1 < kIters) {
                int k0 = (kt+1)*32;
#pragma unroll
                for (int j = 0; j < 2; j++) {
                    int i = tid + j*512, r = i>>3, c = i&7;
                    pa[j] = __ldcg((const float4*)(hp + (size_t)(m0+r)*hstride + hdiroff + k0 + c*4));
                    int grow = (r>>5)*HD + j0 + (r&31);
                    pb[j] = *(const float4*)(Whh + (size_t)grow*HD + k0 + c*4);
                }
            }
#pragma unroll
            for (int kc = 0; kc < 4; kc++) {
                uint32_t af[2][4];
#pragma unroll
                for (int mt = 0; mt < 2; mt++) {
                    int r = mq*32 + mt*16;
                    af[mt][0] = __float_as_uint(As[r+gid  ][kc*8+tig  ]);
                    af[mt][1] = __float_as_uint(As[r+gid+8][kc*8+tig  ]);
                    af[mt][2] = __float_as_uint(As[r+gid  ][kc*8+tig+4]);
                    af[mt][3] = __float_as_uint(As[r+gid+8][kc*8+tig+4]);
                }
#pragma unroll
                for (int nt = 0; nt < 4; nt++) {
                    int br = g*32 + nt*8 + gid;
                    uint32_t b0 = __float_as_uint(Bs[br][kc*8+tig  ]);
                    uint32_t b1 = __float_as_uint(Bs[br][kc*8+tig+4]);
#pragma unroll
                    for (int mt = 0; mt < 2; mt++)
                        mma_tf32(acc[mt][nt][0],acc[mt][nt][1],acc[mt][nt][2],acc[mt][nt][3],
                                 af[mt][0],af[mt][1],af[mt][2],af[mt][3], b0, b1);
                }
            }
            __syncthreads();
        }

        // Two 64-row chunks: stage gates -> elementwise update.
#pragma unroll
        for (int ch = 0; ch < 2; ch++) {
            if ((mq >> 1) == ch) {
                int lm = mq & 1;   // 0..1: which 32-row half of this chunk
#pragma unroll
                for (int mt = 0; mt < 2; mt++) {
                    int rb = lm*32 + mt*16;
#pragma unroll
                    for (int nt = 0; nt < 4; nt++) {
                        int col = g*32 + nt*8 + 2*tig;
                        gsh[rb+gid  ][col  ] = acc[mt][nt][0];
                        gsh[rb+gid  ][col+1] = acc[mt][nt][1];
                        gsh[rb+gid+8][col  ] = acc[mt][nt][2];
                        gsh[rb+gid+8][col+1] = acc[mt][nt][3];
                    }
                }
            }
            __syncthreads();
#pragma unroll
            for (int s = 0; s < 4; s++) {
                int i = tid + s*512;
                int row = i >> 5, jj = i & 31;
                int b = m0 + ch*64 + row, j = j0 + jj;
                size_t igbase = ((size_t)t*B_ + b) * (size_t)(4*HD);
                float gi = gsh[row][      jj] + ig[igbase + 0*HD + j] + bsh[      jj];
                float gf = gsh[row][ 32 + jj] + ig[igbase + 1*HD + j] + bsh[ 32 + jj];
                float gg = gsh[row][ 64 + jj] + ig[igbase + 2*HD + j] + bsh[ 64 + jj];
                float go = gsh[row][ 96 + jj] + ig[igbase + 3*HD + j] + bsh[ 96 + jj];
                float cn = sigm_(gf)*c_reg[ch][s] + sigm_(gi)*tanhf(gg);
                c_reg[ch][s] = cn;
                hn[(size_t)b*hstride + hdiroff + j] = sigm_(go)*tanhf(cn);
            }
            __syncthreads();
        }

        // grid barrier
        __threadfence();
        if (tid == 0) {
            atomicAdd(bar, 1u);
            unsigned target = nblk * (unsigned)(t + 1);
            while (*(volatile unsigned*)bar < target) __nanosleep(64);
            __threadfence();
        }
        __syncthreads();
    }
}

__global__ void classifier_kernel(const float* __restrict__ h, const float* __restrict__ Wl,
                                  const float* __restrict__ bl, float* __restrict__ out)
{
    int wid = (blockIdx.x * blockDim.x + threadIdx.x) >> 5;
    int lane = threadIdx.x & 31;
    if (wid >= B_) return;
    const float* hb = h + (size_t)wid * H2;
    float s0 = 0.f, s1 = 0.f;
    for (int j = lane*4; j < H2; j += 128) {
        float4 hv = *(const float4*)(hb + j);
        float4 w0 = *(const float4*)(Wl + j);
        float4 w1 = *(const float4*)(Wl + H2 + j);
        s0 += hv.x*w0.x + hv.y*w0.y + hv.z*w0.z + hv.w*w0.w;
        s1 += hv.x*w1.x + hv.y*w1.y + hv.z*w1.z + hv.w*w1.w;
    }
#pragma unroll
    for (int o = 16; o > 0; o >>= 1) {
        s0 += __shfl_down_sync(0xFFFFFFFFu, s0, o);
        s1 += __shfl_down_sync(0xFFFFFFFFu, s1, o);
    }
    if (lane == 0) {
        out[wid*2+0] = sigm_(s0 + bl[0]);
        out[wid*2+1] = sigm_(s1 + bl[1]);
    }
}

extern "C" void kernel_launch(void* const* d_in, const int* in_sizes, int n_in,
                              void* d_out, int out_size)
{
    (void)in_sizes; (void)n_in; (void)out_size;
    const float* x     = (const float*)d_in[0];
    const float* Wf_ih = (const float*)d_in[1];
    const float* Wf_hh = (const float*)d_in[2];
    const float* bf    = (const float*)d_in[3];
    const float* Wb_ih = (const float*)d_in[4];
    const float* Wb_hh = (const float*)d_in[5];
    const float* bb    = (const float*)d_in[6];
    const float* Ws_ih = (const float*)d_in[7];
    const float* Ws_hh = (const float*)d_in[8];
    const float* bs    = (const float*)d_in[9];
    const float* Wl    = (const float*)d_in[10];
    const float* bl    = (const float*)d_in[11];
    float* out = (float*)d_out;

    float *p_igf,*p_igb,*p_igs,*p_comb,*p_zero,*p_h2a,*p_h2b;
    unsigned* p_bars;
    cudaGetSymbolAddress((void**)&p_igf,  g_igf);
    cudaGetSymbolAddress((void**)&p_igb,  g_igb);
    cudaGetSymbolAddress((void**)&p_igs,  g_igs);
    cudaGetSymbolAddress((void**)&p_comb, g_comb);
    cudaGetSymbolAddress((void**)&p_zero, g_zero);
    cudaGetSymbolAddress((void**)&p_h2a,  g_h2a);
    cudaGetSymbolAddress((void**)&p_h2b,  g_h2b);
    cudaGetSymbolAddress((void**)&p_bars, g_bars);

    cudaMemsetAsync(p_zero, 0, (size_t)B_*H2*sizeof(float));
    cudaMemsetAsync(p_bars, 0, 2*sizeof(unsigned));

    gemm_tf32_nt<<<dim3(G1/128, (B_*T_)/128), 256>>>(x, Wf_ih, p_igf, B_*T_, G1, D_, 1);
    gemm_tf32_nt<<<dim3(G1/128, (B_*T_)/128), 256>>>(x, Wb_ih, p_igb, B_*T_, G1, D_, 2);

    lstm_scan<H1, 2, 0><<<64, 512>>>(Wf_hh, Wb_hh, bf, bb, p_igf, p_igb,
                                     p_zero, p_comb, nullptr, nullptr, p_bars + 0);

    gemm_tf32_nt<<<dim3(G2/128, (B_*T_)/128), 256>>>(p_comb, Ws_ih, p_igs, B_*T_, G2, 2*H1, 0);

    lstm_scan<H2, 1, 1><<<64, 512>>>(Ws_hh, Ws_hh, bs, bs, p_igs, p_igs,
                                     p_zero, nullptr, p_h2a, p_h2b, p_bars + 1);

    classifier_kernel<<<32, 256>>>(p_h2b, Wl, bl, out);
}

// round 9
// speedup vs baseline: 3.9156x; 3.2923x over previous
#include <cuda_runtime.h>
#include <cuda_bf16.h>
#include <cstdint>
#include <cmath>

#define B_  256
#define T_  128
#define D_  256
#define H1  512
#define G1  (4*H1)
#define H2  1024
#define G2  (4*H2)

// fp32 scratch
__device__ float g_igf [(size_t)T_*B_*G1];
__device__ float g_igb [(size_t)T_*B_*G1];
__device__ float g_igs [(size_t)T_*B_*G2];
__device__ unsigned g_bars[2];
// bf16 scratch
__device__ __nv_bfloat16 g_xb  [(size_t)B_*T_*D_];
__device__ __nv_bfloat16 g_comb[(size_t)T_*B_*(2*H1)];
__device__ __nv_bfloat16 g_zero[B_*H2];
__device__ __nv_bfloat16 g_h2a [B_*H2];
__device__ __nv_bfloat16 g_h2b [B_*H2];
__device__ __nv_bfloat16 g_wfih[(size_t)G1*D_];
__device__ __nv_bfloat16 g_wbih[(size_t)G1*D_];
__device__ __nv_bfloat16 g_wsih[(size_t)G2*(2*H1)];
__device__ __nv_bfloat16 g_wfhh[(size_t)G1*H1];
__device__ __nv_bfloat16 g_wbhh[(size_t)G1*H1];
__device__ __nv_bfloat16 g_wshh[(size_t)G2*H2];

__device__ __forceinline__ void mma_bf16(float& d0, float& d1, float& d2, float& d3,
                                         uint32_t a0, uint32_t a1, uint32_t a2, uint32_t a3,
                                         uint32_t b0, uint32_t b1) {
    asm volatile("mma.sync.aligned.m16n8k16.row.col.f32.bf16.bf16.f32 "
        "{%0,%1,%2,%3}, {%4,%5,%6,%7}, {%8,%9}, {%0,%1,%2,%3};\n"
        : "+f"(d0), "+f"(d1), "+f"(d2), "+f"(d3)
        : "r"(a0), "r"(a1), "r"(a2), "r"(a3), "r"(b0), "r"(b1));
}
__device__ __forceinline__ float sigm_(float x) { return 1.0f / (1.0f + expf(-x)); }

__global__ void f2bf(const float* __restrict__ in, __nv_bfloat16* __restrict__ out, int n) {
    int i = blockIdx.x * blockDim.x + threadIdx.x;
    int stride = gridDim.x * blockDim.x;
    for (; i < n; i += stride) out[i] = __float2bfloat16(in[i]);
}

// ---------------------------------------------------------------------------
// bf16 GEMM: out[orow(m)][n] = sum_k A[m][k]*W[n][k], fp32 out.
// BM=128, BN=128, BK=32(bf16), 256 thr, warps 2x4, warp tile 64x32.
// smem rows = 16 bf16-pairs, stride 20 (conflict-free fragment loads).
// remap: 0 identity; 1 fwd time-major; 2 reversed time-major.
// ---------------------------------------------------------------------------
__global__ void __launch_bounds__(256, 2) gemm_bf16_nt(
    const __nv_bfloat16* __restrict__ A, const __nv_bfloat16* __restrict__ W,
    float* __restrict__ out, int M, int N, int K, int remap)
{
    __shared__ uint32_t As[128][20];
    __shared__ uint32_t Bs[128][20];
    const int tid = threadIdx.x, lane = tid & 31, warp = tid >> 5;
    const int gid = lane >> 2, tig = lane & 3;
    const int wm = warp >> 2, wn = warp & 3;
    const int bm0 = blockIdx.y * 128, bn0 = blockIdx.x * 128;

    float acc[4][4][4];
#pragma unroll
    for (int a = 0; a < 4; a++)
#pragma unroll
        for (int b = 0; b < 4; b++)
#pragma unroll
            for (int c = 0; c < 4; c++) acc[a][b][c] = 0.f;

    const int kIters = K / 32;
    uint4 pa[2], pb[2];
#pragma unroll
    for (int j = 0; j < 2; j++) { int i = tid + j*256, r = i>>2, c = i&3;
        pa[j] = *(const uint4*)(A + (size_t)(bm0+r)*K + c*8);
        pb[j] = *(const uint4*)(W + (size_t)(bn0+r)*K + c*8); }

    for (int kt = 0; kt < kIters; kt++) {
#pragma unroll
        for (int j = 0; j < 2; j++) { int i = tid + j*256, r = i>>2, c = i&3;
            As[r][c*4+0]=pa[j].x; As[r][c*4+1]=pa[j].y; As[r][c*4+2]=pa[j].z; As[r][c*4+3]=pa[j].w;
            Bs[r][c*4+0]=pb[j].x; Bs[r][c*4+1]=pb[j].y; Bs[r][c*4+2]=pb[j].z; Bs[r][c*4+3]=pb[j].w; }
        __syncthreads();
        if (kt + 1 < kIters) {
            int k0 = (kt+1)*32;
#pragma unroll
            for (int j = 0; j < 2; j++) { int i = tid + j*256, r = i>>2, c = i&3;
                pa[j] = *(const uint4*)(A + (size_t)(bm0+r)*K + k0 + c*8);
                pb[j] = *(const uint4*)(W + (size_t)(bn0+r)*K + k0 + c*8); }
        }
#pragma unroll
        for (int kc = 0; kc < 2; kc++) {
            uint32_t af[4][4];
#pragma unroll
            for (int mt = 0; mt < 4; mt++) {
                int r = wm*64 + mt*16;
                af[mt][0] = As[r+gid  ][kc*8+tig  ];
                af[mt][1] = As[r+gid+8][kc*8+tig  ];
                af[mt][2] = As[r+gid  ][kc*8+tig+4];
                af[mt][3] = As[r+gid+8][kc*8+tig+4];
            }
#pragma unroll
            for (int nt = 0; nt < 4; nt++) {
                int cc = wn*32 + nt*8;
                uint32_t b0 = Bs[cc+gid][kc*8+tig  ];
                uint32_t b1 = Bs[cc+gid][kc*8+tig+4];
#pragma unroll
                for (int mt = 0; mt < 4; mt++)
                    mma_bf16(acc[mt][nt][0],acc[mt][nt][1],acc[mt][nt][2],acc[mt][nt][3],
                             af[mt][0],af[mt][1],af[mt][2],af[mt][3], b0, b1);
            }
        }
        __syncthreads();
    }
#pragma unroll
    for (int mt = 0; mt < 4; mt++)
#pragma unroll
        for (int half = 0; half < 2; half++) {
            int m = bm0 + wm*64 + mt*16 + gid + half*8;
            int orow;
            if (remap == 0) orow = m;
            else { int t = m % T_, b = m / T_;
                   orow = ((remap == 1) ? t : (T_-1-t)) * B_ + b; }
            float* op = out + (size_t)orow*N + bn0 + wn*32 + 2*tig;
#pragma unroll
            for (int nt = 0; nt < 4; nt++) {
                op[nt*8+0] = acc[mt][nt][half*2+0];
                op[nt*8+1] = acc[mt][nt][half*2+1];
            }
        }
}

// ---------------------------------------------------------------------------
// Persistent bf16 LSTM scan. grid = 128 blocks (all co-resident), 256 threads.
// Block tile: 64 batch x 32 j x 4 gates (128 gate-cols). 8 warps = (2 mq)x(4 g),
// warp tile 32x32. c-state in registers (8/thread). Grid barrier per step.
// MODE 0: h history in hist (bf16, stride 2*HD, +HD for dir 1).
// MODE 1: ping-pong h2a/h2b (bf16).
// ---------------------------------------------------------------------------
template <int HD, int NDIR, int MODE>
__global__ void __launch_bounds__(256, 1) lstm_scan(
    const __nv_bfloat16* __restrict__ Whh_f, const __nv_bfloat16* __restrict__ Whh_b,
    const float* __restrict__ bias_f, const float* __restrict__ bias_b,
    const float* __restrict__ igf, const float* __restrict__ igb,
    const __nv_bfloat16* __restrict__ h0,
    __nv_bfloat16* __restrict__ hist, __nv_bfloat16* __restrict__ h2a,
    __nv_bfloat16* __restrict__ h2b, unsigned* __restrict__ bar)
{
    __shared__ uint32_t As[64][20];     // 64 batch rows x 32 k (bf16 pairs)
    __shared__ uint32_t Bs[128][20];    // 128 gate rows x 32 k
    __shared__ float gsh[64][129];
    __shared__ float bsh[128];

    const int tid = threadIdx.x, lane = tid & 31, warp = tid >> 5;
    const int gid = lane >> 2, tig = lane & 3;
    const int g = warp & 3, mq = warp >> 2;       // gate, m-half

    const int tilesJ = HD / 32, tilesB = B_ / 64; // 4 batch tiles
    const int dir = blockIdx.x / (tilesB * tilesJ);
    const int rem = blockIdx.x % (tilesB * tilesJ);
    const int m0  = (rem / tilesJ) * 64;
    const int j0  = (rem % tilesJ) * 32;

    const __nv_bfloat16* Whh = dir ? Whh_b : Whh_f;
    const float* bias = dir ? bias_b : bias_f;
    const float* ig   = dir ? igb    : igf;

    const int hstride = (MODE == 0) ? 2*HD : HD;
    const int hdiroff = (MODE == 0) ? dir*HD : 0;

    if (tid < 128) bsh[tid] = bias[(tid>>5)*HD + j0 + (tid&31)];
    __syncthreads();

    float c_reg[8] = {0.f,0.f,0.f,0.f,0.f,0.f,0.f,0.f};
    const int kIters = HD / 32;
    const unsigned nblk = gridDim.x;

    for (int t = 0; t < T_; t++) {
        const __nv_bfloat16* hp;
        __nv_bfloat16* hn;
        if (MODE == 0) {
            hp = (t == 0) ? h0 : hist + (size_t)(t-1)*B_*(2*HD);
            hn = hist + (size_t)t*B_*(2*HD);
        } else {
            hp = (t == 0) ? h0 : ((t & 1) ? h2a : h2b);
            hn = (t & 1) ? h2b : h2a;
        }

        float acc[2][4][4];
#pragma unroll
        for (int a = 0; a < 2; a++)
#pragma unroll
            for (int b = 0; b < 4; b++)
#pragma unroll
                for (int c = 0; c < 4; c++) acc[a][b][c] = 0.f;

        uint4 pa, pb[2];
        {   // prefetch k-tile 0 (h via L2-only: L1 stale across blocks)
            int r = tid >> 2, c = tid & 3;
            pa = __ldcg((const uint4*)(hp + (size_t)(m0+r)*hstride + hdiroff + c*8));
#pragma unroll
            for (int j = 0; j < 2; j++) {
                int i = tid + j*256, rr = i>>2, cc = i&3;
                int grow = (rr>>5)*HD + j0 + (rr&31);
                pb[j] = *(const uint4*)(Whh + (size_t)grow*HD + cc*8);
            }
        }

        for (int kt = 0; kt < kIters; kt++) {
            {
                int r = tid >> 2, c = tid & 3;
                As[r][c*4+0]=pa.x; As[r][c*4+1]=pa.y; As[r][c*4+2]=pa.z; As[r][c*4+3]=pa.w;
#pragma unroll
                for (int j = 0; j < 2; j++) {
                    int i = tid + j*256, rr = i>>2, cc = i&3;
                    Bs[rr][cc*4+0]=pb[j].x; Bs[rr][cc*4+1]=pb[j].y;
                    Bs[rr][cc*4+2]=pb[j].z; Bs[rr][cc*4+3]=pb[j].w;
                }
            }
            __syncthreads();
            if (kt + 1 < kIters) {
                int k0 = (kt+1)*32;
                int r = tid >> 2, c = tid & 3;
                pa = __ldcg((const uint4*)(hp + (size_t)(m0+r)*hstride + hdiroff + k0 + c*8));
#pragma unroll
                for (int j = 0; j < 2; j++) {
                    int i = tid + j*256, rr = i>>2, cc = i&3;
                    int grow = (rr>>5)*HD + j0 + (rr&31);
                    pb[j] = *(const uint4*)(Whh + (size_t)grow*HD + k0 + cc*8);
                }
            }
#pragma unroll
            for (int kc = 0; kc < 2; kc++) {
                uint32_t af[2][4];
#pragma unroll
                for (int mt = 0; mt < 2; mt++) {
                    int r = mq*32 + mt*16;
                    af[mt][0] = As[r+gid  ][kc*8+tig  ];
                    af[mt][1] = As[r+gid+8][kc*8+tig  ];
                    af[mt][2] = As[r+gid  ][kc*8+tig+4];
                    af[mt][3] = As[r+gid+8][kc*8+tig+4];
                }
#pragma unroll
                for (int nt = 0; nt < 4; nt++) {
                    int br = g*32 + nt*8 + gid;
                    uint32_t b0 = Bs[br][kc*8+tig  ];
                    uint32_t b1 = Bs[br][kc*8+tig+4];
#pragma unroll
                    for (int mt = 0; mt < 2; mt++)
                        mma_bf16(acc[mt][nt][0],acc[mt][nt][1],acc[mt][nt][2],acc[mt][nt][3],
                                 af[mt][0],af[mt][1],af[mt][2],af[mt][3], b0, b1);
                }
            }
            __syncthreads();
        }

        // stage gates (rows disjoint per mq, cols disjoint per gate)
#pragma unroll
        for (int mt = 0; mt < 2; mt++) {
            int rb = mq*32 + mt*16;
#pragma unroll
            for (int nt = 0; nt < 4; nt++) {
                int col = g*32 + nt*8 + 2*tig;
                gsh[rb+gid  ][col  ] = acc[mt][nt][0];
                gsh[rb+gid  ][col+1] = acc[mt][nt][1];
                gsh[rb+gid+8][col  ] = acc[mt][nt][2];
                gsh[rb+gid+8][col+1] = acc[mt][nt][3];
            }
        }
        __syncthreads();

#pragma unroll
        for (int s = 0; s < 8; s++) {
            int i = tid + s*256;
            int row = i >> 5, jj = i & 31;
            int b = m0 + row, j = j0 + jj;
            size_t igbase = ((size_t)t*B_ + b) * (size_t)(4*HD);
            float gi = gsh[row][      jj] + ig[igbase + 0*HD + j] + bsh[      jj];
            float gf = gsh[row][ 32 + jj] + ig[igbase + 1*HD + j] + bsh[ 32 + jj];
            float gg = gsh[row][ 64 + jj] + ig[igbase + 2*HD + j] + bsh[ 64 + jj];
            float go = gsh[row][ 96 + jj] + ig[igbase + 3*HD + j] + bsh[ 96 + jj];
            float cn = sigm_(gf)*c_reg[s] + sigm_(gi)*tanhf(gg);
            c_reg[s] = cn;
            hn[(size_t)b*hstride + hdiroff + j] = __float2bfloat16(sigm_(go)*tanhf(cn));
        }

        // grid barrier
        __threadfence();
        __syncthreads();
        if (tid == 0) {
            atomicAdd(bar, 1u);
            unsigned target = nblk * (unsigned)(t + 1);
            while (*(volatile unsigned*)bar < target) __nanosleep(64);
            __threadfence();
        }
        __syncthreads();
    }
}

__global__ void classifier_kernel(const __nv_bfloat16* __restrict__ h,
                                  const float* __restrict__ Wl,
                                  const float* __restrict__ bl, float* __restrict__ out)
{
    int wid = (blockIdx.x * blockDim.x + threadIdx.x) >> 5;
    int lane = threadIdx.x & 31;
    if (wid >= B_) return;
    const __nv_bfloat16* hb = h + (size_t)wid * H2;
    float s0 = 0.f, s1 = 0.f;
    for (int j = lane; j < H2; j += 32) {
        float hv = __bfloat162float(hb[j]);
        s0 += hv * Wl[j];
        s1 += hv * Wl[H2 + j];
    }
#pragma unroll
    for (int o = 16; o > 0; o >>= 1) {
        s0 += __shfl_down_sync(0xFFFFFFFFu, s0, o);
        s1 += __shfl_down_sync(0xFFFFFFFFu, s1, o);
    }
    if (lane == 0) {
        out[wid*2+0] = sigm_(s0 + bl[0]);
        out[wid*2+1] = sigm_(s1 + bl[1]);
    }
}

extern "C" void kernel_launch(void* const* d_in, const int* in_sizes, int n_in,
                              void* d_out, int out_size)
{
    (void)in_sizes; (void)n_in; (void)out_size;
    const float* x     = (const float*)d_in[0];
    const float* Wf_ih = (const float*)d_in[1];
    const float* Wf_hh = (const float*)d_in[2];
    const float* bf    = (const float*)d_in[3];
    const float* Wb_ih = (const float*)d_in[4];
    const float* Wb_hh = (const float*)d_in[5];
    const float* bb    = (const float*)d_in[6];
    const float* Ws_ih = (const float*)d_in[7];
    const float* Ws_hh = (const float*)d_in[8];
    const float* bs    = (const float*)d_in[9];
    const float* Wl    = (const float*)d_in[10];
    const float* bl    = (const float*)d_in[11];
    float* out = (float*)d_out;

    float *p_igf, *p_igb, *p_igs;
    unsigned* p_bars;
    __nv_bfloat16 *p_xb, *p_comb, *p_zero, *p_h2a, *p_h2b;
    __nv_bfloat16 *p_wfih, *p_wbih, *p_wsih, *p_wfhh, *p_wbhh, *p_wshh;
    cudaGetSymbolAddress((void**)&p_igf,  g_igf);
    cudaGetSymbolAddress((void**)&p_igb,  g_igb);
    cudaGetSymbolAddress((void**)&p_igs,  g_igs);
    cudaGetSymbolAddress((void**)&p_bars, g_bars);
    cudaGetSymbolAddress((void**)&p_xb,   g_xb);
    cudaGetSymbolAddress((void**)&p_comb, g_comb);
    cudaGetSymbolAddress((void**)&p_zero, g_zero);
    cudaGetSymbolAddress((void**)&p_h2a,  g_h2a);
    cudaGetSymbolAddress((void**)&p_h2b,  g_h2b);
    cudaGetSymbolAddress((void**)&p_wfih, g_wfih);
    cudaGetSymbolAddress((void**)&p_wbih, g_wbih);
    cudaGetSymbolAddress((void**)&p_wsih, g_wsih);
    cudaGetSymbolAddress((void**)&p_wfhh, g_wfhh);
    cudaGetSymbolAddress((void**)&p_wbhh, g_wbhh);
    cudaGetSymbolAddress((void**)&p_wshh, g_wshh);

    cudaMemsetAsync(p_zero, 0, (size_t)B_*H2*sizeof(__nv_bfloat16));
    cudaMemsetAsync(p_bars, 0, 2*sizeof(unsigned));

    // fp32 -> bf16 conversions (weights + x)
    f2bf<<<2048, 256>>>(x,     p_xb,   B_*T_*D_);
    f2bf<<<512,  256>>>(Wf_ih, p_wfih, G1*D_);
    f2bf<<<512,  256>>>(Wb_ih, p_wbih, G1*D_);
    f2bf<<<2048, 256>>>(Ws_ih, p_wsih, G2*(2*H1));
    f2bf<<<1024, 256>>>(Wf_hh, p_wfhh, G1*H1);
    f2bf<<<1024, 256>>>(Wb_hh, p_wbhh, G1*H1);
    f2bf<<<2048, 256>>>(Ws_hh, p_wshh, G2*H2);

    // Input projections (time-independent), rows remapped to time-major.
    gemm_bf16_nt<<<dim3(G1/128, (B_*T_)/128), 256>>>(p_xb, p_wfih, p_igf, B_*T_, G1, D_, 1);
    gemm_bf16_nt<<<dim3(G1/128, (B_*T_)/128), 256>>>(p_xb, p_wbih, p_igb, B_*T_, G1, D_, 2);

    // BiLSTM layer 1 (persistent, both dirs), h -> comb (bf16).
    lstm_scan<H1, 2, 0><<<128, 256>>>(p_wfhh, p_wbhh, bf, bb, p_igf, p_igb,
                                      p_zero, p_comb, nullptr, nullptr, p_bars + 0);

    // Layer-2 input projection over combined sequence.
    gemm_bf16_nt<<<dim3(G2/128, (B_*T_)/128), 256>>>(p_comb, p_wsih, p_igs, B_*T_, G2, 2*H1, 0);

    // LSTM layer 2 (persistent). Final h lands in h2b (T-1 odd).
    lstm_scan<H2, 1, 1><<<128, 256>>>(p_wshh, p_wshh, bs, bs, p_igs, p_igs,
                                      p_zero, nullptr, p_h2a, p_h2b, p_bars + 1);

    classifier_kernel<<<32, 256>>>(p_h2b, Wl, bl, out);
}

// round 12
// speedup vs baseline: 4.5684x; 1.1667x over previous
#include <cuda_runtime.h>
#include <cuda_bf16.h>
#include <cstdint>
#include <cmath>

#define B_  256
#define T_  128
#define D_  256
#define H1  512
#define G1  (4*H1)
#define H2  1024
#define G2  (4*H2)

// fp32 scratch
__device__ float g_igf [(size_t)T_*B_*G1];
__device__ float g_igb [(size_t)T_*B_*G1];
__device__ float g_igs [(size_t)T_*B_*G2];
__device__ unsigned g_bars[16];
// bf16 scratch
__device__ __nv_bfloat16 g_xb  [(size_t)B_*T_*D_];
__device__ __nv_bfloat16 g_comb[(size_t)T_*B_*(2*H1)];
__device__ __nv_bfloat16 g_zero[B_*H2];
__device__ __nv_bfloat16 g_h2a [B_*H2];
__device__ __nv_bfloat16 g_h2b [B_*H2];
__device__ __nv_bfloat16 g_wfih[(size_t)G1*D_];
__device__ __nv_bfloat16 g_wbih[(size_t)G1*D_];
__device__ __nv_bfloat16 g_wsih[(size_t)G2*(2*H1)];
__device__ __nv_bfloat16 g_wfhh[(size_t)G1*H1];
__device__ __nv_bfloat16 g_wbhh[(size_t)G1*H1];
__device__ __nv_bfloat16 g_wshh[(size_t)G2*H2];

__device__ __forceinline__ void mma_bf16(float& d0, float& d1, float& d2, float& d3,
                                         uint32_t a0, uint32_t a1, uint32_t a2, uint32_t a3,
                                         uint32_t b0, uint32_t b1) {
    asm volatile("mma.sync.aligned.m16n8k16.row.col.f32.bf16.bf16.f32 "
        "{%0,%1,%2,%3}, {%4,%5,%6,%7}, {%8,%9}, {%0,%1,%2,%3};\n"
        : "+f"(d0), "+f"(d1), "+f"(d2), "+f"(d3)
        : "r"(a0), "r"(a1), "r"(a2), "r"(a3), "r"(b0), "r"(b1));
}
__device__ __forceinline__ float sigm_(float x) { return 1.0f / (1.0f + expf(-x)); }

__global__ void f2bf(const float* __restrict__ in, __nv_bfloat16* __restrict__ out, int n) {
    int i = blockIdx.x * blockDim.x + threadIdx.x;
    int stride = gridDim.x * blockDim.x;
    for (; i < n; i += stride) out[i] = __float2bfloat16(in[i]);
}

// ---------------------------------------------------------------------------
// bf16 GEMM (unchanged from R8): out[orow(m)][n] = sum_k A[m][k]*W[n][k].
// ---------------------------------------------------------------------------
__global__ void __launch_bounds__(256, 2) gemm_bf16_nt(
    const __nv_bfloat16* __restrict__ A, const __nv_bfloat16* __restrict__ W,
    float* __restrict__ out, int M, int N, int K, int remap)
{
    __shared__ uint32_t As[128][20];
    __shared__ uint32_t Bs[128][20];
    const int tid = threadIdx.x, lane = tid & 31, warp = tid >> 5;
    const int gid = lane >> 2, tig = lane & 3;
    const int wm = warp >> 2, wn = warp & 3;
    const int bm0 = blockIdx.y * 128, bn0 = blockIdx.x * 128;

    float acc[4][4][4];
#pragma unroll
    for (int a = 0; a < 4; a++)
#pragma unroll
        for (int b = 0; b < 4; b++)
#pragma unroll
            for (int c = 0; c < 4; c++) acc[a][b][c] = 0.f;

    const int kIters = K / 32;
    uint4 pa[2], pb[2];
#pragma unroll
    for (int j = 0; j < 2; j++) { int i = tid + j*256, r = i>>2, c = i&3;
        pa[j] = *(const uint4*)(A + (size_t)(bm0+r)*K + c*8);
        pb[j] = *(const uint4*)(W + (size_t)(bn0+r)*K + c*8); }

    for (int kt = 0; kt < kIters; kt++) {
#pragma unroll
        for (int j = 0; j < 2; j++) { int i = tid + j*256, r = i>>2, c = i&3;
            As[r][c*4+0]=pa[j].x; As[r][c*4+1]=pa[j].y; As[r][c*4+2]=pa[j].z; As[r][c*4+3]=pa[j].w;
            Bs[r][c*4+0]=pb[j].x; Bs[r][c*4+1]=pb[j].y; Bs[r][c*4+2]=pb[j].z; Bs[r][c*4+3]=pb[j].w; }
        __syncthreads();
        if (kt + 1 < kIters) {
            int k0 = (kt+1)*32;
#pragma unroll
            for (int j = 0; j < 2; j++) { int i = tid + j*256, r = i>>2, c = i&3;
                pa[j] = *(const uint4*)(A + (size_t)(bm0+r)*K + k0 + c*8);
                pb[j] = *(const uint4*)(W + (size_t)(bn0+r)*K + k0 + c*8); }
        }
#pragma unroll
        for (int kc = 0; kc < 2; kc++) {
            uint32_t af[4][4];
#pragma unroll
            for (int mt = 0; mt < 4; mt++) {
                int r = wm*64 + mt*16;
                af[mt][0] = As[r+gid  ][kc*8+tig  ];
                af[mt][1] = As[r+gid+8][kc*8+tig  ];
                af[mt][2] = As[r+gid  ][kc*8+tig+4];
                af[mt][3] = As[r+gid+8][kc*8+tig+4];
            }
#pragma unroll
            for (int nt = 0; nt < 4; nt++) {
                int cc = wn*32 + nt*8;
                uint32_t b0 = Bs[cc+gid][kc*8+tig  ];
                uint32_t b1 = Bs[cc+gid][kc*8+tig+4];
#pragma unroll
                for (int mt = 0; mt < 4; mt++)
                    mma_bf16(acc[mt][nt][0],acc[mt][nt][1],acc[mt][nt][2],acc[mt][nt][3],
                             af[mt][0],af[mt][1],af[mt][2],af[mt][3], b0, b1);
            }
        }
        __syncthreads();
    }
#pragma unroll
    for (int mt = 0; mt < 4; mt++)
#pragma unroll
        for (int half = 0; half < 2; half++) {
            int m = bm0 + wm*64 + mt*16 + gid + half*8;
            int orow;
            if (remap == 0) orow = m;
            else { int t = m % T_, b = m / T_;
                   orow = ((remap == 1) ? t : (T_-1-t)) * B_ + b; }
            float* op = out + (size_t)orow*N + bn0 + wn*32 + 2*tig;
#pragma unroll
            for (int nt = 0; nt < 4; nt++) {
                op[nt*8+0] = acc[mt][nt][half*2+0];
                op[nt*8+1] = acc[mt][nt][half*2+1];
            }
        }
}

// ---------------------------------------------------------------------------
// Layer-1 persistent scan: Whh slice RESIDENT in smem (loaded once).
// grid = 128 = dir(2) x mb(4) x jt(16); block 256 thr (8 warps: mq x gate).
// Per step: h -> smem once, then 256 mmas/warp with no syncs; group barrier
// over the 16 blocks sharing (dir, mb).
// dyn smem (u32): wsh[128][260] | ash[64][260] (gsh[64][129] aliases ash).
// ---------------------------------------------------------------------------
#define S1_WSH 0
#define S1_ASH (128*260)
#define S1_SMEM (((128*260)+(64*260))*4)

__global__ void __launch_bounds__(256, 1) lstm_scan1(
    const __nv_bfloat16* __restrict__ Whh_f, const __nv_bfloat16* __restrict__ Whh_b,
    const float* __restrict__ bias_f, const float* __restrict__ bias_b,
    const float* __restrict__ igf, const float* __restrict__ igb,
    const __nv_bfloat16* __restrict__ h0, __nv_bfloat16* __restrict__ hist,
    unsigned* __restrict__ bars)
{
    extern __shared__ uint32_t dsm[];
    uint32_t* wsh = dsm + S1_WSH;
    uint32_t* ash = dsm + S1_ASH;
    float*    gsh = (float*)(dsm + S1_ASH);   // [64][129], aliases ash
    __shared__ float bsh[128];

    const int tid = threadIdx.x, lane = tid & 31, warp = tid >> 5;
    const int gid = lane >> 2, tig = lane & 3;
    const int g = warp & 3, mq = warp >> 2;

    const int dir = blockIdx.x >> 6;
    const int rem = blockIdx.x & 63;
    const int m0  = (rem >> 4) * 64;
    const int j0  = (rem & 15) * 32;
    unsigned* bar = bars + (dir*4 + (rem >> 4));

    const __nv_bfloat16* Whh = dir ? Whh_b : Whh_f;
    const float* bias = dir ? bias_b : bias_f;
    const float* ig   = dir ? igb    : igf;
    const int hstride = 2*H1, hdiroff = dir*H1;

    // Resident weights: 128 gate rows x 512 bf16 (256 u32, stride 260).
#pragma unroll
    for (int j = 0; j < 32; j++) {
        int idx = j*256 + tid, n = idx >> 6, c = idx & 63;
        int grow = (n>>5)*H1 + j0 + (n&31);
        uint4 v = *(const uint4*)(Whh + (size_t)grow*H1 + c*8);
        ((uint4*)(wsh + n*260))[c] = v;
    }
    if (tid < 128) bsh[tid] = bias[(tid>>5)*H1 + j0 + (tid&31)];
    __syncthreads();

    float c_reg[8] = {0.f,0.f,0.f,0.f,0.f,0.f,0.f,0.f};

    for (int t = 0; t < T_; t++) {
        const __nv_bfloat16* hp = (t == 0) ? h0 : hist + (size_t)(t-1)*B_*(2*H1);
        __nv_bfloat16* hn = hist + (size_t)t*B_*(2*H1);

        // h -> smem: 64 rows x 256 u32
#pragma unroll
        for (int j = 0; j < 16; j++) {
            int idx = j*256 + tid, r = idx >> 6, c = idx & 63;
            uint4 v = __ldcg((const uint4*)(hp + (size_t)(m0+r)*hstride + hdiroff + c*8));
            ((uint4*)(ash + r*260))[c] = v;
        }
        __syncthreads();

        float acc[2][4][4];
#pragma unroll
        for (int a = 0; a < 2; a++)
#pragma unroll
            for (int b = 0; b < 4; b++)
#pragma unroll
                for (int c = 0; c < 4; c++) acc[a][b][c] = 0.f;

#pragma unroll 4
        for (int kch = 0; kch < 32; kch++) {
            int kb = kch*8;
            uint32_t af[2][4];
#pragma unroll
            for (int mt = 0; mt < 2; mt++) {
                int r = mq*32 + mt*16;
                af[mt][0] = ash[(r+gid  )*260 + kb+tig  ];
                af[mt][1] = ash[(r+gid+8)*260 + kb+tig  ];
                af[mt][2] = ash[(r+gid  )*260 + kb+tig+4];
                af[mt][3] = ash[(r+gid+8)*260 + kb+tig+4];
            }
#pragma unroll
            for (int nt = 0; nt < 4; nt++) {
                int br = g*32 + nt*8 + gid;
                uint32_t b0 = wsh[br*260 + kb+tig  ];
                uint32_t b1 = wsh[br*260 + kb+tig+4];
#pragma unroll
                for (int mt = 0; mt < 2; mt++)
                    mma_bf16(acc[mt][nt][0],acc[mt][nt][1],acc[mt][nt][2],acc[mt][nt][3],
                             af[mt][0],af[mt][1],af[mt][2],af[mt][3], b0, b1);
            }
        }
        __syncthreads();   // mmas done -> safe to overwrite ash with gsh

#pragma unroll
        for (int mt = 0; mt < 2; mt++) {
            int rb = mq*32 + mt*16;
#pragma unroll
            for (int nt = 0; nt < 4; nt++) {
                int col = g*32 + nt*8 + 2*tig;
                gsh[(rb+gid  )*129 + col  ] = acc[mt][nt][0];
                gsh[(rb+gid  )*129 + col+1] = acc[mt][nt][1];
                gsh[(rb+gid+8)*129 + col  ] = acc[mt][nt][2];
                gsh[(rb+gid+8)*129 + col+1] = acc[mt][nt][3];
            }
        }
        __syncthreads();

#pragma unroll
        for (int s = 0; s < 8; s++) {
            int i = tid + s*256;
            int row = i >> 5, jj = i & 31;
            int b = m0 + row, j = j0 + jj;
            size_t igbase = ((size_t)t*B_ + b) * (size_t)G1;
            float gi = gsh[row*129 +      jj] + ig[igbase + 0*H1 + j] + bsh[      jj];
            float gf = gsh[row*129 + 32 + jj] + ig[igbase + 1*H1 + j] + bsh[ 32 + jj];
            float gg = gsh[row*129 + 64 + jj] + ig[igbase + 2*H1 + j] + bsh[ 64 + jj];
            float go = gsh[row*129 + 96 + jj] + ig[igbase + 3*H1 + j] + bsh[ 96 + jj];
            float cn = sigm_(gf)*c_reg[s] + sigm_(gi)*tanhf(gg);
            c_reg[s] = cn;
            hn[(size_t)b*hstride + hdiroff + j] = __float2bfloat16(sigm_(go)*tanhf(cn));
        }

        // group barrier (16 blocks sharing (dir, mb))
        __threadfence();
        __syncthreads();
        if (tid == 0) {
            atomicAdd(bar, 1u);
            unsigned target = 16u * (unsigned)(t + 1);
            while (*(volatile unsigned*)bar < target) __nanosleep(32);
            __threadfence();
        }
        __syncthreads();
    }
}

// ---------------------------------------------------------------------------
// Layer-2 persistent scan: full h resident per step, weights double-buffered
// from L2 (1 sync per k-tile). grid = 128 = mb(4) x jt(32); 256 thr.
// dyn smem (u32): ash[64][516] (gsh aliases) | bs2[2][128][20].
// ---------------------------------------------------------------------------
#define S2_ASH 0
#define S2_BS  (64*516)
#define S2_SMEM (((64*516)+(2*128*20))*4)

__global__ void __launch_bounds__(256, 1) lstm_scan2(
    const __nv_bfloat16* __restrict__ Whh,
    const float* __restrict__ bias, const float* __restrict__ ig,
    const __nv_bfloat16* __restrict__ h0,
    __nv_bfloat16* __restrict__ h2a, __nv_bfloat16* __restrict__ h2b,
    unsigned* __restrict__ bars)
{
    extern __shared__ uint32_t dsm[];
    uint32_t* ash = dsm + S2_ASH;
    float*    gsh = (float*)(dsm + S2_ASH);
    uint32_t* bs  = dsm + S2_BS;          // [2][128][20]
    __shared__ float bsh[128];

    const int tid = threadIdx.x, lane = tid & 31, warp = tid >> 5;
    const int gid = lane >> 2, tig = lane & 3;
    const int g = warp & 3, mq = warp >> 2;

    const int m0 = (blockIdx.x >> 5) * 64;
    const int j0 = (blockIdx.x & 31) * 32;
    unsigned* bar = bars + 8 + (blockIdx.x >> 5);

    if (tid < 128) bsh[tid] = bias[(tid>>5)*H2 + j0 + (tid&31)];
    __syncthreads();

    float c_reg[8] = {0.f,0.f,0.f,0.f,0.f,0.f,0.f,0.f};

    for (int t = 0; t < T_; t++) {
        const __nv_bfloat16* hp = (t == 0) ? h0 : ((t & 1) ? h2a : h2b);
        __nv_bfloat16* hn = (t & 1) ? h2b : h2a;

        // full h -> smem: 64 rows x 512 u32
#pragma unroll
        for (int j = 0; j < 32; j++) {
            int idx = j*256 + tid, r = idx >> 7, c = idx & 127;
            uint4 v = __ldcg((const uint4*)(hp + (size_t)(m0+r)*H2 + c*8));
            ((uint4*)(ash + r*516))[c] = v;
        }

        float acc[2][4][4];
#pragma unroll
        for (int a = 0; a < 2; a++)
#pragma unroll
            for (int b = 0; b < 4; b++)
#pragma unroll
                for (int c = 0; c < 4; c++) acc[a][b][c] = 0.f;

        // prefetch weight k-tile 0
        uint4 pb[2];
#pragma unroll
        for (int j = 0; j < 2; j++) {
            int idx = j*256 + tid, n = idx >> 2, c = idx & 3;
            int grow = (n>>5)*H2 + j0 + (n&31);
            pb[j] = *(const uint4*)(Whh + (size_t)grow*H2 + c*8);
        }
        __syncthreads();   // covers both ash ready and bs free

        for (int kt = 0; kt < 32; kt++) {
            int buf = kt & 1;
#pragma unroll
            for (int j = 0; j < 2; j++) {
                int idx = j*256 + tid, n = idx >> 2, c = idx & 3;
                ((uint4*)(bs + buf*2560 + n*20))[c] = pb[j];
            }
            __syncthreads();
            if (kt + 1 < 32) {
                int k0 = (kt+1)*32;
#pragma unroll
                for (int j = 0; j < 2; j++) {
                    int idx = j*256 + tid, n = idx >> 2, c = idx & 3;
                    int grow = (n>>5)*H2 + j0 + (n&31);
                    pb[j] = *(const uint4*)(Whh + (size_t)grow*H2 + k0 + c*8);
                }
            }
#pragma unroll
            for (int kc = 0; kc < 2; kc++) {
                int kb = kt*16 + kc*8;
                uint32_t af[2][4];
#pragma unroll
                for (int mt = 0; mt < 2; mt++) {
                    int r = mq*32 + mt*16;
                    af[mt][0] = ash[(r+gid  )*516 + kb+tig  ];
                    af[mt][1] = ash[(r+gid+8)*516 + kb+tig  ];
                    af[mt][2] = ash[(r+gid  )*516 + kb+tig+4];
                    af[mt][3] = ash[(r+gid+8)*516 + kb+tig+4];
                }
#pragma unroll
                for (int nt = 0; nt < 4; nt++) {
                    int br = g*32 + nt*8 + gid;
                    uint32_t b0 = bs[buf*2560 + br*20 + kc*8+tig  ];
                    uint32_t b1 = bs[buf*2560 + br*20 + kc*8+tig+4];
#pragma unroll
                    for (int mt = 0; mt < 2; mt++)
                        mma_bf16(acc[mt][nt][0],acc[mt][nt][1],acc[mt][nt][2],acc[mt][nt][3],
                                 af[mt][0],af[mt][1],af[mt][2],af[mt][3], b0, b1);
                }
            }
        }
        __syncthreads();   // mmas done -> overwrite ash with gsh

#pragma unroll
        for (int mt = 0; mt < 2; mt++) {
            int rb = mq*32 + mt*16;
#pragma unroll
            for (int nt = 0; nt < 4; nt++) {
                int col = g*32 + nt*8 + 2*tig;
                gsh[(rb+gid  )*129 + col  ] = acc[mt][nt][0];
                gsh[(rb+gid  )*129 + col+1] = acc[mt][nt][1];
                gsh[(rb+gid+8)*129 + col  ] = acc[mt][nt][2];
                gsh[(rb+gid+8)*129 + col+1] = acc[mt][nt][3];
            }
        }
        __syncthreads();

#pragma unroll
        for (int s = 0; s < 8; s++) {
            int i = tid + s*256;
            int row = i >> 5, jj = i & 31;
            int b = m0 + row, j = j0 + jj;
            size_t igbase = ((size_t)t*B_ + b) * (size_t)G2;
            float gi = gsh[row*129 +      jj] + ig[igbase + 0*H2 + j] + bsh[      jj];
            float gf = gsh[row*129 + 32 + jj] + ig[igbase + 1*H2 + j] + bsh[ 32 + jj];
            float gg = gsh[row*129 + 64 + jj] + ig[igbase + 2*H2 + j] + bsh[ 64 + jj];
            float go = gsh[row*129 + 96 + jj] + ig[igbase + 3*H2 + j] + bsh[ 96 + jj];
            float cn = sigm_(gf)*c_reg[s] + sigm_(gi)*tanhf(gg);
            c_reg[s] = cn;
            hn[(size_t)b*H2 + j] = __float2bfloat16(sigm_(go)*tanhf(cn));
        }

        // group barrier (32 blocks sharing mb)
        __threadfence();
        __syncthreads();
        if (tid == 0) {
            atomicAdd(bar, 1u);
            unsigned target = 32u * (unsigned)(t + 1);
            while (*(volatile unsigned*)bar < target) __nanosleep(32);
            __threadfence();
        }
        __syncthreads();
    }
}

__global__ void classifier_kernel(const __nv_bfloat16* __restrict__ h,
                                  const float* __restrict__ Wl,
                                  const float* __restrict__ bl, float* __restrict__ out)
{
    int wid = (blockIdx.x * blockDim.x + threadIdx.x) >> 5;
    int lane = threadIdx.x & 31;
    if (wid >= B_) return;
    const __nv_bfloat16* hb = h + (size_t)wid * H2;
    float s0 = 0.f, s1 = 0.f;
    for (int j = lane; j < H2; j += 32) {
        float hv = __bfloat162float(hb[j]);
        s0 += hv * Wl[j];
        s1 += hv * Wl[H2 + j];
    }
#pragma unroll
    for (int o = 16; o > 0; o >>= 1) {
        s0 += __shfl_down_sync(0xFFFFFFFFu, s0, o);
        s1 += __shfl_down_sync(0xFFFFFFFFu, s1, o);
    }
    if (lane == 0) {
        out[wid*2+0] = sigm_(s0 + bl[0]);
        out[wid*2+1] = sigm_(s1 + bl[1]);
    }
}

extern "C" void kernel_launch(void* const* d_in, const int* in_sizes, int n_in,
                              void* d_out, int out_size)
{
    (void)in_sizes; (void)n_in; (void)out_size;
    const float* x     = (const float*)d_in[0];
    const float* Wf_ih = (const float*)d_in[1];
    const float* Wf_hh = (const float*)d_in[2];
    const float* bf    = (const float*)d_in[3];
    const float* Wb_ih = (const float*)d_in[4];
    const float* Wb_hh = (const float*)d_in[5];
    const float* bb    = (const float*)d_in[6];
    const float* Ws_ih = (const float*)d_in[7];
    const float* Ws_hh = (const float*)d_in[8];
    const float* bs    = (const float*)d_in[9];
    const float* Wl    = (const float*)d_in[10];
    const float* bl    = (const float*)d_in[11];
    float* out = (float*)d_out;

    float *p_igf, *p_igb, *p_igs;
    unsigned* p_bars;
    __nv_bfloat16 *p_xb, *p_comb, *p_zero, *p_h2a, *p_h2b;
    __nv_bfloat16 *p_wfih, *p_wbih, *p_wsih, *p_wfhh, *p_wbhh, *p_wshh;
    cudaGetSymbolAddress((void**)&p_igf,  g_igf);
    cudaGetSymbolAddress((void**)&p_igb,  g_igb);
    cudaGetSymbolAddress((void**)&p_igs,  g_igs);
    cudaGetSymbolAddress((void**)&p_bars, g_bars);
    cudaGetSymbolAddress((void**)&p_xb,   g_xb);
    cudaGetSymbolAddress((void**)&p_comb, g_comb);
    cudaGetSymbolAddress((void**)&p_zero, g_zero);
    cudaGetSymbolAddress((void**)&p_h2a,  g_h2a);
    cudaGetSymbolAddress((void**)&p_h2b,  g_h2b);
    cudaGetSymbolAddress((void**)&p_wfih, g_wfih);
    cudaGetSymbolAddress((void**)&p_wbih, g_wbih);
    cudaGetSymbolAddress((void**)&p_wsih, g_wsih);
    cudaGetSymbolAddress((void**)&p_wfhh, g_wfhh);
    cudaGetSymbolAddress((void**)&p_wbhh, g_wbhh);
    cudaGetSymbolAddress((void**)&p_wshh, g_wshh);

    cudaFuncSetAttribute(lstm_scan1, cudaFuncAttributeMaxDynamicSharedMemorySize, S1_SMEM);
    cudaFuncSetAttribute(lstm_scan2, cudaFuncAttributeMaxDynamicSharedMemorySize, S2_SMEM);

    cudaMemsetAsync(p_zero, 0, (size_t)B_*H2*sizeof(__nv_bfloat16));
    cudaMemsetAsync(p_bars, 0, 16*sizeof(unsigned));

    f2bf<<<2048, 256>>>(x,     p_xb,   B_*T_*D_);
    f2bf<<<512,  256>>>(Wf_ih, p_wfih, G1*D_);
    f2bf<<<512,  256>>>(Wb_ih, p_wbih, G1*D_);
    f2bf<<<2048, 256>>>(Ws_ih, p_wsih, G2*(2*H1));
    f2bf<<<1024, 256>>>(Wf_hh, p_wfhh, G1*H1);
    f2bf<<<1024, 256>>>(Wb_hh, p_wbhh, G1*H1);
    f2bf<<<2048, 256>>>(Ws_hh, p_wshh, G2*H2);

    gemm_bf16_nt<<<dim3(G1/128, (B_*T_)/128), 256>>>(p_xb, p_wfih, p_igf, B_*T_, G1, D_, 1);
    gemm_bf16_nt<<<dim3(G1/128, (B_*T_)/128), 256>>>(p_xb, p_wbih, p_igb, B_*T_, G1, D_, 2);

    lstm_scan1<<<128, 256, S1_SMEM>>>(p_wfhh, p_wbhh, bf, bb, p_igf, p_igb,
                                      p_zero, p_comb, p_bars);

    gemm_bf16_nt<<<dim3(G2/128, (B_*T_)/128), 256>>>(p_comb, p_wsih, p_igs, B_*T_, G2, 2*H1, 0);

    lstm_scan2<<<128, 256, S2_SMEM>>>(p_wshh, bs, p_igs, p_zero, p_h2a, p_h2b, p_bars);

    classifier_kernel<<<32, 256>>>(p_h2b, Wl, bl, out);
}

// round 13
// speedup vs baseline: 5.4705x; 1.1975x over previous
#include <cuda_runtime.h>
#include <cuda_bf16.h>
#include <cstdint>
#include <cmath>

#define B_  256
#define T_  128
#define D_  256
#define H1  512
#define G1  (4*H1)
#define H2  1024
#define G2  (4*H2)

// fp32 scratch
__device__ float g_igf [(size_t)T_*B_*G1];
__device__ float g_igb [(size_t)T_*B_*G1];
__device__ float g_igs [(size_t)T_*B_*G2];
__device__ unsigned g_bars[16];
// bf16 scratch
__device__ __nv_bfloat16 g_xb  [(size_t)B_*T_*D_];
__device__ __nv_bfloat16 g_comb[(size_t)T_*B_*(2*H1)];
__device__ __nv_bfloat16 g_zero[B_*H2];
__device__ __nv_bfloat16 g_h2a [B_*H2];
__device__ __nv_bfloat16 g_h2b [B_*H2];
__device__ __nv_bfloat16 g_wfih[(size_t)G1*D_];
__device__ __nv_bfloat16 g_wbih[(size_t)G1*D_];
__device__ __nv_bfloat16 g_wsih[(size_t)G2*(2*H1)];
__device__ __nv_bfloat16 g_wfhh[(size_t)G1*H1];
__device__ __nv_bfloat16 g_wbhh[(size_t)G1*H1];
__device__ __nv_bfloat16 g_wshh[(size_t)G2*H2];

__device__ __forceinline__ void mma_bf16(float& d0, float& d1, float& d2, float& d3,
                                         uint32_t a0, uint32_t a1, uint32_t a2, uint32_t a3,
                                         uint32_t b0, uint32_t b1) {
    asm volatile("mma.sync.aligned.m16n8k16.row.col.f32.bf16.bf16.f32 "
        "{%0,%1,%2,%3}, {%4,%5,%6,%7}, {%8,%9}, {%0,%1,%2,%3};\n"
        : "+f"(d0), "+f"(d1), "+f"(d2), "+f"(d3)
        : "r"(a0), "r"(a1), "r"(a2), "r"(a3), "r"(b0), "r"(b1));
}
__device__ __forceinline__ float sigm_(float x) { return 1.0f / (1.0f + expf(-x)); }

// ---------------------------------------------------------------------------
// Fused fp32->bf16 conversion for all 7 tensors (one launch).
// ---------------------------------------------------------------------------
struct SegT { const float* s; __nv_bfloat16* d; int n; };
struct Seg7 { SegT seg[7]; };

__global__ void f2bf_all(Seg7 p) {
    int stride = gridDim.x * blockDim.x;
    int base = blockIdx.x * blockDim.x + threadIdx.x;
#pragma unroll
    for (int k = 0; k < 7; k++) {
        const float* s = p.seg[k].s;
        __nv_bfloat16* d = p.seg[k].d;
        int n = p.seg[k].n;
        for (int i = base; i < n; i += stride) d[i] = __float2bfloat16(s[i]);
    }
}

// ---------------------------------------------------------------------------
// bf16 GEMM (unchanged): out[orow(m)][n] = sum_k A[m][k]*W[n][k].
// ---------------------------------------------------------------------------
__global__ void __launch_bounds__(256, 2) gemm_bf16_nt(
    const __nv_bfloat16* __restrict__ A, const __nv_bfloat16* __restrict__ W,
    float* __restrict__ out, int M, int N, int K, int remap)
{
    __shared__ uint32_t As[128][20];
    __shared__ uint32_t Bs[128][20];
    const int tid = threadIdx.x, lane = tid & 31, warp = tid >> 5;
    const int gid = lane >> 2, tig = lane & 3;
    const int wm = warp >> 2, wn = warp & 3;
    const int bm0 = blockIdx.y * 128, bn0 = blockIdx.x * 128;

    float acc[4][4][4];
#pragma unroll
    for (int a = 0; a < 4; a++)
#pragma unroll
        for (int b = 0; b < 4; b++)
#pragma unroll
            for (int c = 0; c < 4; c++) acc[a][b][c] = 0.f;

    const int kIters = K / 32;
    uint4 pa[2], pb[2];
#pragma unroll
    for (int j = 0; j < 2; j++) { int i = tid + j*256, r = i>>2, c = i&3;
        pa[j] = *(const uint4*)(A + (size_t)(bm0+r)*K + c*8);
        pb[j] = *(const uint4*)(W + (size_t)(bn0+r)*K + c*8); }

    for (int kt = 0; kt < kIters; kt++) {
#pragma unroll
        for (int j = 0; j < 2; j++) { int i = tid + j*256, r = i>>2, c = i&3;
            As[r][c*4+0]=pa[j].x; As[r][c*4+1]=pa[j].y; As[r][c*4+2]=pa[j].z; As[r][c*4+3]=pa[j].w;
            Bs[r][c*4+0]=pb[j].x; Bs[r][c*4+1]=pb[j].y; Bs[r][c*4+2]=pb[j].z; Bs[r][c*4+3]=pb[j].w; }
        __syncthreads();
        if (kt + 1 < kIters) {
            int k0 = (kt+1)*32;
#pragma unroll
            for (int j = 0; j < 2; j++) { int i = tid + j*256, r = i>>2, c = i&3;
                pa[j] = *(const uint4*)(A + (size_t)(bm0+r)*K + k0 + c*8);
                pb[j] = *(const uint4*)(W + (size_t)(bn0+r)*K + k0 + c*8); }
        }
#pragma unroll
        for (int kc = 0; kc < 2; kc++) {
            uint32_t af[4][4];
#pragma unroll
            for (int mt = 0; mt < 4; mt++) {
                int r = wm*64 + mt*16;
                af[mt][0] = As[r+gid  ][kc*8+tig  ];
                af[mt][1] = As[r+gid+8][kc*8+tig  ];
                af[mt][2] = As[r+gid  ][kc*8+tig+4];
                af[mt][3] = As[r+gid+8][kc*8+tig+4];
            }
#pragma unroll
            for (int nt = 0; nt < 4; nt++) {
                int cc = wn*32 + nt*8;
                uint32_t b0 = Bs[cc+gid][kc*8+tig  ];
                uint32_t b1 = Bs[cc+gid][kc*8+tig+4];
#pragma unroll
                for (int mt = 0; mt < 4; mt++)
                    mma_bf16(acc[mt][nt][0],acc[mt][nt][1],acc[mt][nt][2],acc[mt][nt][3],
                             af[mt][0],af[mt][1],af[mt][2],af[mt][3], b0, b1);
            }
        }
        __syncthreads();
    }
#pragma unroll
    for (int mt = 0; mt < 4; mt++)
#pragma unroll
        for (int half = 0; half < 2; half++) {
            int m = bm0 + wm*64 + mt*16 + gid + half*8;
            int orow;
            if (remap == 0) orow = m;
            else { int t = m % T_, b = m / T_;
                   orow = ((remap == 1) ? t : (T_-1-t)) * B_ + b; }
            float* op = out + (size_t)orow*N + bn0 + wn*32 + 2*tig;
#pragma unroll
            for (int nt = 0; nt < 4; nt++) {
                op[nt*8+0] = acc[mt][nt][half*2+0];
                op[nt*8+1] = acc[mt][nt][half*2+1];
            }
        }
}

// ---------------------------------------------------------------------------
// Layer-1 persistent scan (resident weights) + ig register prefetch.
// grid = 128 = dir(2) x mb(4) x jt(16); 256 thr.
// ---------------------------------------------------------------------------
#define S1_WSH 0
#define S1_ASH (128*260)
#define S1_SMEM (((128*260)+(64*260))*4)

__global__ void __launch_bounds__(256, 1) lstm_scan1(
    const __nv_bfloat16* __restrict__ Whh_f, const __nv_bfloat16* __restrict__ Whh_b,
    const float* __restrict__ bias_f, const float* __restrict__ bias_b,
    const float* __restrict__ igf, const float* __restrict__ igb,
    const __nv_bfloat16* __restrict__ h0, __nv_bfloat16* __restrict__ hist,
    unsigned* __restrict__ bars)
{
    extern __shared__ uint32_t dsm[];
    uint32_t* wsh = dsm + S1_WSH;
    uint32_t* ash = dsm + S1_ASH;
    float*    gsh = (float*)(dsm + S1_ASH);   // [64][129], aliases ash
    __shared__ float bsh[128];

    const int tid = threadIdx.x, lane = tid & 31, warp = tid >> 5;
    const int gid = lane >> 2, tig = lane & 3;
    const int g = warp & 3, mq = warp >> 2;

    const int dir = blockIdx.x >> 6;
    const int rem = blockIdx.x & 63;
    const int m0  = (rem >> 4) * 64;
    const int j0  = (rem & 15) * 32;
    unsigned* bar = bars + (dir*4 + (rem >> 4));

    const __nv_bfloat16* Whh = dir ? Whh_b : Whh_f;
    const float* bias = dir ? bias_b : bias_f;
    const float* ig   = dir ? igb    : igf;
    const int hstride = 2*H1, hdiroff = dir*H1;

#pragma unroll
    for (int j = 0; j < 32; j++) {
        int idx = j*256 + tid, n = idx >> 6, c = idx & 63;
        int grow = (n>>5)*H1 + j0 + (n&31);
        uint4 v = *(const uint4*)(Whh + (size_t)grow*H1 + c*8);
        ((uint4*)(wsh + n*260))[c] = v;
    }
    if (tid < 128) bsh[tid] = bias[(tid>>5)*H1 + j0 + (tid&31)];
    __syncthreads();

    float c_reg[8] = {0.f,0.f,0.f,0.f,0.f,0.f,0.f,0.f};
    const int erow = tid >> 5, ejj = tid & 31;     // elementwise indexing
    const int ej = j0 + ejj;

    for (int t = 0; t < T_; t++) {
        const __nv_bfloat16* hp = (t == 0) ? h0 : hist + (size_t)(t-1)*B_*(2*H1);
        __nv_bfloat16* hn = hist + (size_t)t*B_*(2*H1);

        // ig prefetch: 32 independent LDGs issued before the mma loop.
        float pf[8][4];
#pragma unroll
        for (int s = 0; s < 8; s++) {
            int b = m0 + erow + s*8;
            size_t igbase = ((size_t)t*B_ + b) * (size_t)G1;
#pragma unroll
            for (int gg2 = 0; gg2 < 4; gg2++)
                pf[s][gg2] = ig[igbase + gg2*H1 + ej];
        }

        // h -> smem
#pragma unroll
        for (int j = 0; j < 16; j++) {
            int idx = j*256 + tid, r = idx >> 6, c = idx & 63;
            uint4 v = __ldcg((const uint4*)(hp + (size_t)(m0+r)*hstride + hdiroff + c*8));
            ((uint4*)(ash + r*260))[c] = v;
        }
        __syncthreads();

        float acc[2][4][4];
#pragma unroll
        for (int a = 0; a < 2; a++)
#pragma unroll
            for (int b = 0; b < 4; b++)
#pragma unroll
                for (int c = 0; c < 4; c++) acc[a][b][c] = 0.f;

#pragma unroll 4
        for (int kch = 0; kch < 32; kch++) {
            int kb = kch*8;
            uint32_t af[2][4];
#pragma unroll
            for (int mt = 0; mt < 2; mt++) {
                int r = mq*32 + mt*16;
                af[mt][0] = ash[(r+gid  )*260 + kb+tig  ];
                af[mt][1] = ash[(r+gid+8)*260 + kb+tig  ];
                af[mt][2] = ash[(r+gid  )*260 + kb+tig+4];
                af[mt][3] = ash[(r+gid+8)*260 + kb+tig+4];
            }
#pragma unroll
            for (int nt = 0; nt < 4; nt++) {
                int br = g*32 + nt*8 + gid;
                uint32_t b0 = wsh[br*260 + kb+tig  ];
                uint32_t b1 = wsh[br*260 + kb+tig+4];
#pragma unroll
                for (int mt = 0; mt < 2; mt++)
                    mma_bf16(acc[mt][nt][0],acc[mt][nt][1],acc[mt][nt][2],acc[mt][nt][3],
                             af[mt][0],af[mt][1],af[mt][2],af[mt][3], b0, b1);
            }
        }
        __syncthreads();

#pragma unroll
        for (int mt = 0; mt < 2; mt++) {
            int rb = mq*32 + mt*16;
#pragma unroll
            for (int nt = 0; nt < 4; nt++) {
                int col = g*32 + nt*8 + 2*tig;
                gsh[(rb+gid  )*129 + col  ] = acc[mt][nt][0];
                gsh[(rb+gid  )*129 + col+1] = acc[mt][nt][1];
                gsh[(rb+gid+8)*129 + col  ] = acc[mt][nt][2];
                gsh[(rb+gid+8)*129 + col+1] = acc[mt][nt][3];
            }
        }
        __syncthreads();

#pragma unroll
        for (int s = 0; s < 8; s++) {
            int row = erow + s*8;
            int b = m0 + row;
            float gi = gsh[row*129 +      ejj] + pf[s][0] + bsh[      ejj];
            float gf = gsh[row*129 + 32 + ejj] + pf[s][1] + bsh[ 32 + ejj];
            float gg = gsh[row*129 + 64 + ejj] + pf[s][2] + bsh[ 64 + ejj];
            float go = gsh[row*129 + 96 + ejj] + pf[s][3] + bsh[ 96 + ejj];
            float cn = sigm_(gf)*c_reg[s] + sigm_(gi)*tanhf(gg);
            c_reg[s] = cn;
            hn[(size_t)b*hstride + hdiroff + ej] = __float2bfloat16(sigm_(go)*tanhf(cn));
        }

        __threadfence();
        __syncthreads();
        if (tid == 0) {
            atomicAdd(bar, 1u);
            unsigned target = 16u * (unsigned)(t + 1);
            while (*(volatile unsigned*)bar < target) __nanosleep(32);
            __threadfence();
        }
        __syncthreads();
    }
}

// ---------------------------------------------------------------------------
// Layer-2 persistent scan: h resident, weights double-buffered at BK=64
// (16 syncs/step, conflict-free stride 36) + ig register prefetch.
// grid = 128 = mb(4) x jt(32); 256 thr.
// dyn smem (u32): ash[64][516] (gsh aliases) | bs[2][128][36].
// ---------------------------------------------------------------------------
#define S2_ASH 0
#define S2_BS  (64*516)
#define S2_SMEM (((64*516)+(2*128*36))*4)

__global__ void __launch_bounds__(256, 1) lstm_scan2(
    const __nv_bfloat16* __restrict__ Whh,
    const float* __restrict__ bias, const float* __restrict__ ig,
    const __nv_bfloat16* __restrict__ h0,
    __nv_bfloat16* __restrict__ h2a, __nv_bfloat16* __restrict__ h2b,
    unsigned* __restrict__ bars)
{
    extern __shared__ uint32_t dsm[];
    uint32_t* ash = dsm + S2_ASH;
    float*    gsh = (float*)(dsm + S2_ASH);
    uint32_t* bs  = dsm + S2_BS;          // [2][128][36]
    __shared__ float bsh[128];

    const int tid = threadIdx.x, lane = tid & 31, warp = tid >> 5;
    const int gid = lane >> 2, tig = lane & 3;
    const int g = warp & 3, mq = warp >> 2;

    const int m0 = (blockIdx.x >> 5) * 64;
    const int j0 = (blockIdx.x & 31) * 32;
    unsigned* bar = bars + 8 + (blockIdx.x >> 5);

    if (tid < 128) bsh[tid] = bias[(tid>>5)*H2 + j0 + (tid&31)];
    __syncthreads();

    float c_reg[8] = {0.f,0.f,0.f,0.f,0.f,0.f,0.f,0.f};
    const int erow = tid >> 5, ejj = tid & 31;
    const int ej = j0 + ejj;

    for (int t = 0; t < T_; t++) {
        const __nv_bfloat16* hp = (t == 0) ? h0 : ((t & 1) ? h2a : h2b);
        __nv_bfloat16* hn = (t & 1) ? h2b : h2a;

        // ig prefetch
        float pf[8][4];
#pragma unroll
        for (int s = 0; s < 8; s++) {
            int b = m0 + erow + s*8;
            size_t igbase = ((size_t)t*B_ + b) * (size_t)G2;
#pragma unroll
            for (int gg2 = 0; gg2 < 4; gg2++)
                pf[s][gg2] = ig[igbase + gg2*H2 + ej];
        }

        // full h -> smem
#pragma unroll
        for (int j = 0; j < 32; j++) {
            int idx = j*256 + tid, r = idx >> 7, c = idx & 127;
            uint4 v = __ldcg((const uint4*)(hp + (size_t)(m0+r)*H2 + c*8));
            ((uint4*)(ash + r*516))[c] = v;
        }

        float acc[2][4][4];
#pragma unroll
        for (int a = 0; a < 2; a++)
#pragma unroll
            for (int b = 0; b < 4; b++)
#pragma unroll
                for (int c = 0; c < 4; c++) acc[a][b][c] = 0.f;

        // prefetch weight k-tile 0 (BK=64: 4 uint4/thread)
        uint4 pb[4];
#pragma unroll
        for (int j = 0; j < 4; j++) {
            int idx = j*256 + tid, n = idx >> 3, c = idx & 7;
            int grow = (n>>5)*H2 + j0 + (n&31);
            pb[j] = *(const uint4*)(Whh + (size_t)grow*H2 + c*8);
        }
        __syncthreads();   // ash ready + bs free

        for (int kt = 0; kt < 16; kt++) {
            int buf = kt & 1;
#pragma unroll
            for (int j = 0; j < 4; j++) {
                int idx = j*256 + tid, n = idx >> 3, c = idx & 7;
                ((uint4*)(bs + buf*4608 + n*36))[c] = pb[j];
            }
            __syncthreads();
            if (kt + 1 < 16) {
                int k0 = (kt+1)*64;
#pragma unroll
                for (int j = 0; j < 4; j++) {
                    int idx = j*256 + tid, n = idx >> 3, c = idx & 7;
                    int grow = (n>>5)*H2 + j0 + (n&31);
                    pb[j] = *(const uint4*)(Whh + (size_t)grow*H2 + k0 + c*8);
                }
            }
#pragma unroll
            for (int kc = 0; kc < 4; kc++) {
                int kb = kt*32 + kc*8;
                uint32_t af[2][4];
#pragma unroll
                for (int mt = 0; mt < 2; mt++) {
                    int r = mq*32 + mt*16;
                    af[mt][0] = ash[(r+gid  )*516 + kb+tig  ];
                    af[mt][1] = ash[(r+gid+8)*516 + kb+tig  ];
                    af[mt][2] = ash[(r+gid  )*516 + kb+tig+4];
                    af[mt][3] = ash[(r+gid+8)*516 + kb+tig+4];
                }
#pragma unroll
                for (int nt = 0; nt < 4; nt++) {
                    int br = g*32 + nt*8 + gid;
                    uint32_t b0 = bs[buf*4608 + br*36 + kc*8+tig  ];
                    uint32_t b1 = bs[buf*4608 + br*36 + kc*8+tig+4];
#pragma unroll
                    for (int mt = 0; mt < 2; mt++)
                        mma_bf16(acc[mt][nt][0],acc[mt][nt][1],acc[mt][nt][2],acc[mt][nt][3],
                                 af[mt][0],af[mt][1],af[mt][2],af[mt][3], b0, b1);
                }
            }
        }
        __syncthreads();

#pragma unroll
        for (int mt = 0; mt < 2; mt++) {
            int rb = mq*32 + mt*16;
#pragma unroll
            for (int nt = 0; nt < 4; nt++) {
                int col = g*32 + nt*8 + 2*tig;
                gsh[(rb+gid  )*129 + col  ] = acc[mt][nt][0];
                gsh[(rb+gid  )*129 + col+1] = acc[mt][nt][1];
                gsh[(rb+gid+8)*129 + col  ] = acc[mt][nt][2];
                gsh[(rb+gid+8)*129 + col+1] = acc[mt][nt][3];
            }
        }
        __syncthreads();

#pragma unroll
        for (int s = 0; s < 8; s++) {
            int row = erow + s*8;
            int b = m0 + row;
            float gi = gsh[row*129 +      ejj] + pf[s][0] + bsh[      ejj];
            float gf = gsh[row*129 + 32 + ejj] + pf[s][1] + bsh[ 32 + ejj];
            float gg = gsh[row*129 + 64 + ejj] + pf[s][2] + bsh[ 64 + ejj];
            float go = gsh[row*129 + 96 + ejj] + pf[s][3] + bsh[ 96 + ejj];
            float cn = sigm_(gf)*c_reg[s] + sigm_(gi)*tanhf(gg);
            c_reg[s] = cn;
            hn[(size_t)b*H2 + ej] = __float2bfloat16(sigm_(go)*tanhf(cn));
        }

        __threadfence();
        __syncthreads();
        if (tid == 0) {
            atomicAdd(bar, 1u);
            unsigned target = 32u * (unsigned)(t + 1);
            while (*(volatile unsigned*)bar < target) __nanosleep(32);
            __threadfence();
        }
        __syncthreads();
    }
}

__global__ void classifier_kernel(const __nv_bfloat16* __restrict__ h,
                                  const float* __restrict__ Wl,
                                  const float* __restrict__ bl, float* __restrict__ out)
{
    int wid = (blockIdx.x * blockDim.x + threadIdx.x) >> 5;
    int lane = threadIdx.x & 31;
    if (wid >= B_) return;
    const __nv_bfloat16* hb = h + (size_t)wid * H2;
    float s0 = 0.f, s1 = 0.f;
    for (int j = lane; j < H2; j += 32) {
        float hv = __bfloat162float(hb[j]);
        s0 += hv * Wl[j];
        s1 += hv * Wl[H2 + j];
    }
#pragma unroll
    for (int o = 16; o > 0; o >>= 1) {
        s0 += __shfl_down_sync(0xFFFFFFFFu, s0, o);
        s1 += __shfl_down_sync(0xFFFFFFFFu, s1, o);
    }
    if (lane == 0) {
        out[wid*2+0] = sigm_(s0 + bl[0]);
        out[wid*2+1] = sigm_(s1 + bl[1]);
    }
}

extern "C" void kernel_launch(void* const* d_in, const int* in_sizes, int n_in,
                              void* d_out, int out_size)
{
    (void)in_sizes; (void)n_in; (void)out_size;
    const float* x     = (const float*)d_in[0];
    const float* Wf_ih = (const float*)d_in[1];
    const float* Wf_hh = (const float*)d_in[2];
    const float* bf    = (const float*)d_in[3];
    const float* Wb_ih = (const float*)d_in[4];
    const float* Wb_hh = (const float*)d_in[5];
    const float* bb    = (const float*)d_in[6];
    const float* Ws_ih = (const float*)d_in[7];
    const float* Ws_hh = (const float*)d_in[8];
    const float* bs    = (const float*)d_in[9];
    const float* Wl    = (const float*)d_in[10];
    const float* bl    = (const float*)d_in[11];
    float* out = (float*)d_out;

    float *p_igf, *p_igb, *p_igs;
    unsigned* p_bars;
    __nv_bfloat16 *p_xb, *p_comb, *p_zero, *p_h2a, *p_h2b;
    __nv_bfloat16 *p_wfih, *p_wbih, *p_wsih, *p_wfhh, *p_wbhh, *p_wshh;
    cudaGetSymbolAddress((void**)&p_igf,  g_igf);
    cudaGetSymbolAddress((void**)&p_igb,  g_igb);
    cudaGetSymbolAddress((void**)&p_igs,  g_igs);
    cudaGetSymbolAddress((void**)&p_bars, g_bars);
    cudaGetSymbolAddress((void**)&p_xb,   g_xb);
    cudaGetSymbolAddress((void**)&p_comb, g_comb);
    cudaGetSymbolAddress((void**)&p_zero, g_zero);
    cudaGetSymbolAddress((void**)&p_h2a,  g_h2a);
    cudaGetSymbolAddress((void**)&p_h2b,  g_h2b);
    cudaGetSymbolAddress((void**)&p_wfih, g_wfih);
    cudaGetSymbolAddress((void**)&p_wbih, g_wbih);
    cudaGetSymbolAddress((void**)&p_wsih, g_wsih);
    cudaGetSymbolAddress((void**)&p_wfhh, g_wfhh);
    cudaGetSymbolAddress((void**)&p_wbhh, g_wbhh);
    cudaGetSymbolAddress((void**)&p_wshh, g_wshh);

    cudaFuncSetAttribute(lstm_scan1, cudaFuncAttributeMaxDynamicSharedMemorySize, S1_SMEM);
    cudaFuncSetAttribute(lstm_scan2, cudaFuncAttributeMaxDynamicSharedMemorySize, S2_SMEM);

    cudaMemsetAsync(p_zero, 0, (size_t)B_*H2*sizeof(__nv_bfloat16));
    cudaMemsetAsync(p_bars, 0, 16*sizeof(unsigned));

    Seg7 sp;
    sp.seg[0] = { x,     p_xb,   B_*T_*D_ };
    sp.seg[1] = { Wf_ih, p_wfih, G1*D_ };
    sp.seg[2] = { Wb_ih, p_wbih, G1*D_ };
    sp.seg[3] = { Ws_ih, p_wsih, G2*(2*H1) };
    sp.seg[4] = { Wf_hh, p_wfhh, G1*H1 };
    sp.seg[5] = { Wb_hh, p_wbhh, G1*H1 };
    sp.seg[6] = { Ws_hh, p_wshh, G2*H2 };
    f2bf_all<<<1184, 256>>>(sp);

    gemm_bf16_nt<<<dim3(G1/128, (B_*T_)/128), 256>>>(p_xb, p_wfih, p_igf, B_*T_, G1, D_, 1);
    gemm_bf16_nt<<<dim3(G1/128, (B_*T_)/128), 256>>>(p_xb, p_wbih, p_igb, B_*T_, G1, D_, 2);

    lstm_scan1<<<128, 256, S1_SMEM>>>(p_wfhh, p_wbhh, bf, bb, p_igf, p_igb,
                                      p_zero, p_comb, p_bars);

    gemm_bf16_nt<<<dim3(G2/128, (B_*T_)/128), 256>>>(p_comb, p_wsih, p_igs, B_*T_, G2, 2*H1, 0);

    lstm_scan2<<<128, 256, S2_SMEM>>>(p_wshh, bs, p_igs, p_zero, p_h2a, p_h2b, p_bars);

    classifier_kernel<<<32, 256>>>(p_h2b, Wl, bl, out);
}

// round 15
// speedup vs baseline: 5.9503x; 1.0877x over previous
#include <cuda_runtime.h>
#include <cuda_bf16.h>
#include <cstdint>
#include <cmath>

#define B_  256
#define T_  128
#define D_  256
#define H1  512
#define G1  (4*H1)
#define H2  1024
#define G2  (4*H2)

// scratch
__device__ unsigned g_bars[16];
__device__ __nv_bfloat16 g_igf [(size_t)T_*B_*G1];
__device__ __nv_bfloat16 g_igb [(size_t)T_*B_*G1];
__device__ __nv_bfloat16 g_igs [(size_t)T_*B_*G2];
__device__ __nv_bfloat16 g_xb  [(size_t)B_*T_*D_];
__device__ __nv_bfloat16 g_comb[(size_t)T_*B_*(2*H1)];
__device__ __nv_bfloat16 g_zero[B_*H2];
__device__ __nv_bfloat16 g_h2a [B_*H2];
__device__ __nv_bfloat16 g_h2b [B_*H2];
__device__ __nv_bfloat16 g_wfih[(size_t)G1*D_];
__device__ __nv_bfloat16 g_wbih[(size_t)G1*D_];
__device__ __nv_bfloat16 g_wsih[(size_t)G2*(2*H1)];
__device__ __nv_bfloat16 g_wfhh[(size_t)G1*H1];
__device__ __nv_bfloat16 g_wbhh[(size_t)G1*H1];
__device__ __nv_bfloat16 g_wshh[(size_t)G2*H2];

__device__ __forceinline__ void mma_bf16(float& d0, float& d1, float& d2, float& d3,
                                         uint32_t a0, uint32_t a1, uint32_t a2, uint32_t a3,
                                         uint32_t b0, uint32_t b1) {
    asm volatile("mma.sync.aligned.m16n8k16.row.col.f32.bf16.bf16.f32 "
        "{%0,%1,%2,%3}, {%4,%5,%6,%7}, {%8,%9}, {%0,%1,%2,%3};\n"
        : "+f"(d0), "+f"(d1), "+f"(d2), "+f"(d3)
        : "r"(a0), "r"(a1), "r"(a2), "r"(a3), "r"(b0), "r"(b1));
}
__device__ __forceinline__ float tanh_ap(float x) {
    float y; asm("tanh.approx.f32 %0, %1;" : "=f"(y) : "f"(x)); return y;
}
__device__ __forceinline__ float sigm_ap(float x) { return 0.5f * tanh_ap(0.5f * x) + 0.5f; }
__device__ __forceinline__ float sigm_ex(float x) { return 1.0f / (1.0f + expf(-x)); }

// ---------------------------------------------------------------------------
struct SegT { const float* s; __nv_bfloat16* d; int n; };
struct Seg7 { SegT seg[7]; };

__global__ void f2bf_all(Seg7 p) {
    int stride = gridDim.x * blockDim.x;
    int base = blockIdx.x * blockDim.x + threadIdx.x;
#pragma unroll
    for (int k = 0; k < 7; k++) {
        const float* s = p.seg[k].s;
        __nv_bfloat16* d = p.seg[k].d;
        int n = p.seg[k].n;
        for (int i = base; i < n; i += stride) d[i] = __float2bfloat16(s[i]);
    }
}

// ---------------------------------------------------------------------------
// bf16 GEMM, bf16 output: out[orow(m)][n] = sum_k A[m][k]*W[n][k].
// ---------------------------------------------------------------------------
__global__ void __launch_bounds__(256, 2) gemm_bf16_nt(
    const __nv_bfloat16* __restrict__ A, const __nv_bfloat16* __restrict__ W,
    __nv_bfloat16* __restrict__ out, int M, int N, int K, int remap)
{
    __shared__ uint32_t As[128][20];
    __shared__ uint32_t Bs[128][20];
    const int tid = threadIdx.x, lane = tid & 31, warp = tid >> 5;
    const int gid = lane >> 2, tig = lane & 3;
    const int wm = warp >> 2, wn = warp & 3;
    const int bm0 = blockIdx.y * 128, bn0 = blockIdx.x * 128;

    float acc[4][4][4];
#pragma unroll
    for (int a = 0; a < 4; a++)
#pragma unroll
        for (int b = 0; b < 4; b++)
#pragma unroll
            for (int c = 0; c < 4; c++) acc[a][b][c] = 0.f;

    const int kIters = K / 32;
    uint4 pa[2], pb[2];
#pragma unroll
    for (int j = 0; j < 2; j++) { int i = tid + j*256, r = i>>2, c = i&3;
        pa[j] = *(const uint4*)(A + (size_t)(bm0+r)*K + c*8);
        pb[j] = *(const uint4*)(W + (size_t)(bn0+r)*K + c*8); }

    for (int kt = 0; kt < kIters; kt++) {
#pragma unroll
        for (int j = 0; j < 2; j++) { int i = tid + j*256, r = i>>2, c = i&3;
            As[r][c*4+0]=pa[j].x; As[r][c*4+1]=pa[j].y; As[r][c*4+2]=pa[j].z; As[r][c*4+3]=pa[j].w;
            Bs[r][c*4+0]=pb[j].x; Bs[r][c*4+1]=pb[j].y; Bs[r][c*4+2]=pb[j].z; Bs[r][c*4+3]=pb[j].w; }
        __syncthreads();
        if (kt + 1 < kIters) {
            int k0 = (kt+1)*32;
#pragma unroll
            for (int j = 0; j < 2; j++) { int i = tid + j*256, r = i>>2, c = i&3;
                pa[j] = *(const uint4*)(A + (size_t)(bm0+r)*K + k0 + c*8);
                pb[j] = *(const uint4*)(W + (size_t)(bn0+r)*K + k0 + c*8); }
        }
#pragma unroll
        for (int kc = 0; kc < 2; kc++) {
            uint32_t af[4][4];
#pragma unroll
            for (int mt = 0; mt < 4; mt++) {
                int r = wm*64 + mt*16;
                af[mt][0] = As[r+gid  ][kc*8+tig  ];
                af[mt][1] = As[r+gid+8][kc*8+tig  ];
                af[mt][2] = As[r+gid  ][kc*8+tig+4];
                af[mt][3] = As[r+gid+8][kc*8+tig+4];
            }
#pragma unroll
            for (int nt = 0; nt < 4; nt++) {
                int cc = wn*32 + nt*8;
                uint32_t b0 = Bs[cc+gid][kc*8+tig  ];
                uint32_t b1 = Bs[cc+gid][kc*8+tig+4];
#pragma unroll
                for (int mt = 0; mt < 4; mt++)
                    mma_bf16(acc[mt][nt][0],acc[mt][nt][1],acc[mt][nt][2],acc[mt][nt][3],
                             af[mt][0],af[mt][1],af[mt][2],af[mt][3], b0, b1);
            }
        }
        __syncthreads();
    }
#pragma unroll
    for (int mt = 0; mt < 4; mt++)
#pragma unroll
        for (int half = 0; half < 2; half++) {
            int m = bm0 + wm*64 + mt*16 + gid + half*8;
            int orow;
            if (remap == 0) orow = m;
            else { int t = m % T_, b = m / T_;
                   orow = ((remap == 1) ? t : (T_-1-t)) * B_ + b; }
            __nv_bfloat16* op = out + (size_t)orow*N + bn0 + wn*32 + 2*tig;
#pragma unroll
            for (int nt = 0; nt < 4; nt++) {
                __nv_bfloat162 v;
                v.x = __float2bfloat16(acc[mt][nt][half*2+0]);
                v.y = __float2bfloat16(acc[mt][nt][half*2+1]);
                *(__nv_bfloat162*)(op + nt*8) = v;
            }
        }
}

// ---------------------------------------------------------------------------
// Layer-1 persistent scan, 512 thr, K-split warps (kh2 x mq2 x g4), resident W.
// grid = 128 = dir(2) x mb(4) x jt(16). gsh[2] planes alias ash.
// ---------------------------------------------------------------------------
#define S1_ASH (128*260)
#define S1_SMEM (((128*260)+(64*260))*4)

__global__ void __launch_bounds__(512, 1) lstm_scan1(
    const __nv_bfloat16* __restrict__ Whh_f, const __nv_bfloat16* __restrict__ Whh_b,
    const float* __restrict__ bias_f, const float* __restrict__ bias_b,
    const __nv_bfloat16* __restrict__ igf, const __nv_bfloat16* __restrict__ igb,
    const __nv_bfloat16* __restrict__ h0, __nv_bfloat16* __restrict__ hist,
    unsigned* __restrict__ bars)
{
    extern __shared__ uint32_t dsm[];
    uint32_t* wsh = dsm;
    uint32_t* ash = dsm + S1_ASH;
    float*    gsh = (float*)(dsm + S1_ASH);   // [2][64][129]
    __shared__ float bsh[128];

    const int tid = threadIdx.x, lane = tid & 31, warp = tid >> 5;
    const int gid = lane >> 2, tig = lane & 3;
    const int kh = warp >> 3, mq = (warp >> 2) & 1, g = warp & 3;

    const int dir = blockIdx.x >> 6;
    const int rem = blockIdx.x & 63;
    const int m0  = (rem >> 4) * 64;
    const int j0  = (rem & 15) * 32;
    unsigned* bar = bars + (dir*4 + (rem >> 4));

    const __nv_bfloat16* Whh = dir ? Whh_b : Whh_f;
    const float* bias = dir ? bias_b : bias_f;
    const __nv_bfloat16* ig = dir ? igb : igf;
    const int hstride = 2*H1, hdiroff = dir*H1;

    // resident weights: 128 gate rows x 256 u32
#pragma unroll
    for (int j = 0; j < 16; j++) {
        int idx = j*512 + tid, n = idx >> 6, c = idx & 63;
        int grow = (n>>5)*H1 + j0 + (n&31);
        ((uint4*)(wsh + n*260))[c] = *(const uint4*)(Whh + (size_t)grow*H1 + c*8);
    }
    if (tid < 128) bsh[tid] = bias[(tid>>5)*H1 + j0 + (tid&31)];
    __syncthreads();

    float c_reg[4] = {0.f,0.f,0.f,0.f};
    const int erow = tid >> 5, ejj = tid & 31;
    const int ej = j0 + ejj;

    for (int t = 0; t < T_; t++) {
        const __nv_bfloat16* hp = (t == 0) ? h0 : hist + (size_t)(t-1)*B_*(2*H1);
        __nv_bfloat16* hn = hist + (size_t)t*B_*(2*H1);

        // ig prefetch (bf16)
        float pf[4][4];
#pragma unroll
        for (int s = 0; s < 4; s++) {
            int b = m0 + erow + s*16;
            size_t igbase = ((size_t)t*B_ + b) * (size_t)G1;
#pragma unroll
            for (int gg2 = 0; gg2 < 4; gg2++)
                pf[s][gg2] = __bfloat162float(ig[igbase + gg2*H1 + ej]);
        }

        // h -> smem
#pragma unroll
        for (int j = 0; j < 8; j++) {
            int idx = j*512 + tid, r = idx >> 6, c = idx & 63;
            uint4 v = __ldcg((const uint4*)(hp + (size_t)(m0+r)*hstride + hdiroff + c*8));
            ((uint4*)(ash + r*260))[c] = v;
        }
        __syncthreads();

        float acc[2][4][4];
#pragma unroll
        for (int a = 0; a < 2; a++)
#pragma unroll
            for (int b = 0; b < 4; b++)
#pragma unroll
                for (int c = 0; c < 4; c++) acc[a][b][c] = 0.f;

#pragma unroll 4
        for (int kc = 0; kc < 16; kc++) {
            int kb = kh*128 + kc*8;
            uint32_t af[2][4];
#pragma unroll
            for (int mt = 0; mt < 2; mt++) {
                int r = mq*32 + mt*16;
                af[mt][0] = ash[(r+gid  )*260 + kb+tig  ];
                af[mt][1] = ash[(r+gid+8)*260 + kb+tig  ];
                af[mt][2] = ash[(r+gid  )*260 + kb+tig+4];
                af[mt][3] = ash[(r+gid+8)*260 + kb+tig+4];
            }
#pragma unroll
            for (int nt = 0; nt < 4; nt++) {
                int br = g*32 + nt*8 + gid;
                uint32_t b0 = wsh[br*260 + kb+tig  ];
                uint32_t b1 = wsh[br*260 + kb+tig+4];
#pragma unroll
                for (int mt = 0; mt < 2; mt++)
                    mma_bf16(acc[mt][nt][0],acc[mt][nt][1],acc[mt][nt][2],acc[mt][nt][3],
                             af[mt][0],af[mt][1],af[mt][2],af[mt][3], b0, b1);
            }
        }
        __syncthreads();   // mmas done -> overwrite ash with gsh planes

        float* gp = gsh + kh*64*129;
#pragma unroll
        for (int mt = 0; mt < 2; mt++) {
            int rb = mq*32 + mt*16;
#pragma unroll
            for (int nt = 0; nt < 4; nt++) {
                int col = g*32 + nt*8 + 2*tig;
                gp[(rb+gid  )*129 + col  ] = acc[mt][nt][0];
                gp[(rb+gid  )*129 + col+1] = acc[mt][nt][1];
                gp[(rb+gid+8)*129 + col  ] = acc[mt][nt][2];
                gp[(rb+gid+8)*129 + col+1] = acc[mt][nt][3];
            }
        }
        __syncthreads();

#pragma unroll
        for (int s = 0; s < 4; s++) {
            int row = erow + s*16;
            int b = m0 + row;
            float gi = gsh[row*129 +      ejj] + gsh[64*129 + row*129 +      ejj] + pf[s][0] + bsh[      ejj];
            float gf = gsh[row*129 + 32 + ejj] + gsh[64*129 + row*129 + 32 + ejj] + pf[s][1] + bsh[ 32 + ejj];
            float gg = gsh[row*129 + 64 + ejj] + gsh[64*129 + row*129 + 64 + ejj] + pf[s][2] + bsh[ 64 + ejj];
            float go = gsh[row*129 + 96 + ejj] + gsh[64*129 + row*129 + 96 + ejj] + pf[s][3] + bsh[ 96 + ejj];
            float cn = sigm_ap(gf)*c_reg[s] + sigm_ap(gi)*tanh_ap(gg);
            c_reg[s] = cn;
            hn[(size_t)b*hstride + hdiroff + ej] = __float2bfloat16(sigm_ap(go)*tanh_ap(cn));
        }

        __threadfence();
        __syncthreads();
        if (tid == 0) {
            atomicAdd(bar, 1u);
            unsigned target = 16u * (unsigned)(t + 1);
            while (*(volatile unsigned*)bar < target) __nanosleep(32);
            __threadfence();
        }
        __syncthreads();
    }
}

// ---------------------------------------------------------------------------
// Layer-2 persistent scan, 512 thr, K-split warps; h resident; weights
// streamed in 8 double-buffered 128-k slabs (8 syncs/step).
// grid = 128 = mb(4) x jt(32).
// dyn smem (u32): ash[64][516] (gsh[2] planes alias) | bs[2][128][68].
// ---------------------------------------------------------------------------
#define S2_BS  (64*516)
#define S2_SMEM (((64*516)+(2*128*68))*4)

__global__ void __launch_bounds__(512, 1) lstm_scan2(
    const __nv_bfloat16* __restrict__ Whh,
    const float* __restrict__ bias, const __nv_bfloat16* __restrict__ ig,
    const __nv_bfloat16* __restrict__ h0,
    __nv_bfloat16* __restrict__ h2a, __nv_bfloat16* __restrict__ h2b,
    unsigned* __restrict__ bars)
{
    extern __shared__ uint32_t dsm[];
    uint32_t* ash = dsm;
    float*    gsh = (float*)dsm;          // [2][64][129]
    uint32_t* bs  = dsm + S2_BS;          // [2][128][68]
    __shared__ float bsh[128];

    const int tid = threadIdx.x, lane = tid & 31, warp = tid >> 5;
    const int gid = lane >> 2, tig = lane & 3;
    const int kh = warp >> 3, mq = (warp >> 2) & 1, g = warp & 3;

    const int m0 = (blockIdx.x >> 5) * 64;
    const int j0 = (blockIdx.x & 31) * 32;
    unsigned* bar = bars + 8 + (blockIdx.x >> 5);

    if (tid < 128) bsh[tid] = bias[(tid>>5)*H2 + j0 + (tid&31)];
    __syncthreads();

    float c_reg[4] = {0.f,0.f,0.f,0.f};
    const int erow = tid >> 5, ejj = tid & 31;
    const int ej = j0 + ejj;

    for (int t = 0; t < T_; t++) {
        const __nv_bfloat16* hp = (t == 0) ? h0 : ((t & 1) ? h2a : h2b);
        __nv_bfloat16* hn = (t & 1) ? h2b : h2a;

        // ig prefetch
        float pf[4][4];
#pragma unroll
        for (int s = 0; s < 4; s++) {
            int b = m0 + erow + s*16;
            size_t igbase = ((size_t)t*B_ + b) * (size_t)G2;
#pragma unroll
            for (int gg2 = 0; gg2 < 4; gg2++)
                pf[s][gg2] = __bfloat162float(ig[igbase + gg2*H2 + ej]);
        }

        // full h -> smem: 64 rows x 512 u32
#pragma unroll
        for (int j = 0; j < 16; j++) {
            int idx = j*512 + tid, r = idx >> 7, c = idx & 127;
            uint4 v = __ldcg((const uint4*)(hp + (size_t)(m0+r)*H2 + c*8));
            ((uint4*)(ash + r*516))[c] = v;
        }

        // prefetch weight slab 0 (128 rows x 128 bf16)
        uint4 pb[4];
#pragma unroll
        for (int j = 0; j < 4; j++) {
            int idx = j*512 + tid, n = idx >> 4, c = idx & 15;
            int grow = (n>>5)*H2 + j0 + (n&31);
            pb[j] = *(const uint4*)(Whh + (size_t)grow*H2 + c*8);
        }
        __syncthreads();   // ash ready + bs free

        float acc[2][4][4];
#pragma unroll
        for (int a = 0; a < 2; a++)
#pragma unroll
            for (int b = 0; b < 4; b++)
#pragma unroll
                for (int c = 0; c < 4; c++) acc[a][b][c] = 0.f;

        for (int si = 0; si < 8; si++) {
            int buf = si & 1;
#pragma unroll
            for (int j = 0; j < 4; j++) {
                int idx = j*512 + tid, n = idx >> 4, c = idx & 15;
                ((uint4*)(bs + buf*128*68 + n*68))[c] = pb[j];
            }
            __syncthreads();
            if (si + 1 < 8) {
                int k0 = (si+1)*128;
#pragma unroll
                for (int j = 0; j < 4; j++) {
                    int idx = j*512 + tid, n = idx >> 4, c = idx & 15;
                    int grow = (n>>5)*H2 + j0 + (n&31);
                    pb[j] = *(const uint4*)(Whh + (size_t)grow*H2 + k0 + c*8);
                }
            }
#pragma unroll
            for (int kc = 0; kc < 4; kc++) {
                int kba = si*64 + kh*32 + kc*8;   // ash u32 col
                int kbb = kh*32 + kc*8;           // bs u32 col
                uint32_t af[2][4];
#pragma unroll
                for (int mt = 0; mt < 2; mt++) {
                    int r = mq*32 + mt*16;
                    af[mt][0] = ash[(r+gid  )*516 + kba+tig  ];
                    af[mt][1] = ash[(r+gid+8)*516 + kba+tig  ];
                    af[mt][2] = ash[(r+gid  )*516 + kba+tig+4];
                    af[mt][3] = ash[(r+gid+8)*516 + kba+tig+4];
                }
#pragma unroll
                for (int nt = 0; nt < 4; nt++) {
                    int br = g*32 + nt*8 + gid;
                    uint32_t b0 = bs[buf*128*68 + br*68 + kbb+tig  ];
                    uint32_t b1 = bs[buf*128*68 + br*68 + kbb+tig+4];
#pragma unroll
                    for (int mt = 0; mt < 2; mt++)
                        mma_bf16(acc[mt][nt][0],acc[mt][nt][1],acc[mt][nt][2],acc[mt][nt][3],
                                 af[mt][0],af[mt][1],af[mt][2],af[mt][3], b0, b1);
                }
            }
            // no sync: next si stores into the other buffer
        }
        __syncthreads();   // mmas done -> overwrite ash with gsh planes

        float* gp = gsh + kh*64*129;
#pragma unroll
        for (int mt = 0; mt < 2; mt++) {
            int rb = mq*32 + mt*16;
#pragma unroll
            for (int nt = 0; nt < 4; nt++) {
                int col = g*32 + nt*8 + 2*tig;
                gp[(rb+gid  )*129 + col  ] = acc[mt][nt][0];
                gp[(rb+gid  )*129 + col+1] = acc[mt][nt][1];
                gp[(rb+gid+8)*129 + col  ] = acc[mt][nt][2];
                gp[(rb+gid+8)*129 + col+1] = acc[mt][nt][3];
            }
        }
        __syncthreads();

#pragma unroll
        for (int s = 0; s < 4; s++) {
            int row = erow + s*16;
            int b = m0 + row;
            float gi = gsh[row*129 +      ejj] + gsh[64*129 + row*129 +      ejj] + pf[s][0] + bsh[      ejj];
            float gf = gsh[row*129 + 32 + ejj] + gsh[64*129 + row*129 + 32 + ejj] + pf[s][1] + bsh[ 32 + ejj];
            float gg = gsh[row*129 + 64 + ejj] + gsh[64*129 + row*129 + 64 + ejj] + pf[s][2] + bsh[ 64 + ejj];
            float go = gsh[row*129 + 96 + ejj] + gsh[64*129 + row*129 + 96 + ejj] + pf[s][3] + bsh[ 96 + ejj];
            float cn = sigm_ap(gf)*c_reg[s] + sigm_ap(gi)*tanh_ap(gg);
            c_reg[s] = cn;
            hn[(size_t)b*H2 + ej] = __float2bfloat16(sigm_ap(go)*tanh_ap(cn));
        }

        __threadfence();
        __syncthreads();
        if (tid == 0) {
            atomicAdd(bar, 1u);
            unsigned target = 32u * (unsigned)(t + 1);
            while (*(volatile unsigned*)bar < target) __nanosleep(32);
            __threadfence();
        }
        __syncthreads();
    }
}

__global__ void classifier_kernel(const __nv_bfloat16* __restrict__ h,
                                  const float* __restrict__ Wl,
                                  const float* __restrict__ bl, float* __restrict__ out)
{
    int wid = (blockIdx.x * blockDim.x + threadIdx.x) >> 5;
    int lane = threadIdx.x & 31;
    if (wid >= B_) return;
    const __nv_bfloat16* hb = h + (size_t)wid * H2;
    float s0 = 0.f, s1 = 0.f;
    for (int j = lane; j < H2; j += 32) {
        float hv = __bfloat162float(hb[j]);
        s0 += hv * Wl[j];
        s1 += hv * Wl[H2 + j];
    }
#pragma unroll
    for (int o = 16; o > 0; o >>= 1) {
        s0 += __shfl_down_sync(0xFFFFFFFFu, s0, o);
        s1 += __shfl_down_sync(0xFFFFFFFFu, s1, o);
    }
    if (lane == 0) {
        out[wid*2+0] = sigm_ex(s0 + bl[0]);
        out[wid*2+1] = sigm_ex(s1 + bl[1]);
    }
}

extern "C" void kernel_launch(void* const* d_in, const int* in_sizes, int n_in,
                              void* d_out, int out_size)
{
    (void)in_sizes; (void)n_in; (void)out_size;
    const float* x     = (const float*)d_in[0];
    const float* Wf_ih = (const float*)d_in[1];
    const float* Wf_hh = (const float*)d_in[2];
    const float* bf    = (const float*)d_in[3];
    const float* Wb_ih = (const float*)d_in[4];
    const float* Wb_hh = (const float*)d_in[5];
    const float* bb    = (const float*)d_in[6];
    const float* Ws_ih = (const float*)d_in[7];
    const float* Ws_hh = (const float*)d_in[8];
    const float* bs    = (const float*)d_in[9];
    const float* Wl    = (const float*)d_in[10];
    const float* bl    = (const float*)d_in[11];
    float* out = (float*)d_out;

    unsigned* p_bars;
    __nv_bfloat16 *p_igf, *p_igb, *p_igs;
    __nv_bfloat16 *p_xb, *p_comb, *p_zero, *p_h2a, *p_h2b;
    __nv_bfloat16 *p_wfih, *p_wbih, *p_wsih, *p_wfhh, *p_wbhh, *p_wshh;
    cudaGetSymbolAddress((void**)&p_igf,  g_igf);
    cudaGetSymbolAddress((void**)&p_igb,  g_igb);
    cudaGetSymbolAddress((void**)&p_igs,  g_igs);
    cudaGetSymbolAddress((void**)&p_bars, g_bars);
    cudaGetSymbolAddress((void**)&p_xb,   g_xb);
    cudaGetSymbolAddress((void**)&p_comb, g_comb);
    cudaGetSymbolAddress((void**)&p_zero, g_zero);
    cudaGetSymbolAddress((void**)&p_h2a,  g_h2a);
    cudaGetSymbolAddress((void**)&p_h2b,  g_h2b);
    cudaGetSymbolAddress((void**)&p_wfih, g_wfih);
    cudaGetSymbolAddress((void**)&p_wbih, g_wbih);
    cudaGetSymbolAddress((void**)&p_wsih, g_wsih);
    cudaGetSymbolAddress((void**)&p_wfhh, g_wfhh);
    cudaGetSymbolAddress((void**)&p_wbhh, g_wbhh);
    cudaGetSymbolAddress((void**)&p_wshh, g_wshh);

    cudaFuncSetAttribute(lstm_scan1, cudaFuncAttributeMaxDynamicSharedMemorySize, S1_SMEM);
    cudaFuncSetAttribute(lstm_scan2, cudaFuncAttributeMaxDynamicSharedMemorySize, S2_SMEM);

    cudaMemsetAsync(p_zero, 0, (size_t)B_*H2*sizeof(__nv_bfloat16));
    cudaMemsetAsync(p_bars, 0, 16*sizeof(unsigned));

    Seg7 sp;
    sp.seg[0] = { x,     p_xb,   B_*T_*D_ };
    sp.seg[1] = { Wf_ih, p_wfih, G1*D_ };
    sp.seg[2] = { Wb_ih, p_wbih, G1*D_ };
    sp.seg[3] = { Ws_ih, p_wsih, G2*(2*H1) };
    sp.seg[4] = { Wf_hh, p_wfhh, G1*H1 };
    sp.seg[5] = { Wb_hh, p_wbhh, G1*H1 };
    sp.seg[6] = { Ws_hh, p_wshh, G2*H2 };
    f2bf_all<<<1184, 256>>>(sp);

    gemm_bf16_nt<<<dim3(G1/128, (B_*T_)/128), 256>>>(p_xb, p_wfih, p_igf, B_*T_, G1, D_, 1);
    gemm_bf16_nt<<<dim3(G1/128, (B_*T_)/128), 256>>>(p_xb, p_wbih, p_igb, B_*T_, G1, D_, 2);

    lstm_scan1<<<128, 512, S1_SMEM>>>(p_wfhh, p_wbhh, bf, bb, p_igf, p_igb,
                                      p_zero, p_comb, p_bars);

    gemm_bf16_nt<<<dim3(G2/128, (B_*T_)/128), 256>>>(p_comb, p_wsih, p_igs, B_*T_, G2, 2*H1, 0);

    lstm_scan2<<<128, 512, S2_SMEM>>>(p_wshh, bs, p_igs, p_zero, p_h2a, p_h2b, p_bars);

    classifier_kernel<<<32, 256>>>(p_h2b, Wl, bl, out);
}